// round 1
// baseline (speedup 1.0000x reference)
#include <cuda_runtime.h>
#include <math.h>

// ---------------- problem constants ----------------
#define S_LEN   2048
#define BATCH   2
#define T_TOK   (BATCH * S_LEN)     // 4096 tokens
#define HIDDEN  2048
#define QLORA   1536
#define KVLORA  512
#define NHEADS  16
#define NOPE    128
#define ROPE_D  64
#define QHD     192                 // NOPE + ROPE
#define VHD     128
#define KVW     576                 // KVLORA + ROPE

// ---------------- scratch (device globals; no allocs allowed) ----------------
__device__ float g_qa  [T_TOK * QLORA];        // q latent (rmsnormed in place)
__device__ float g_q   [T_TOK * NHEADS * QHD]; // per-head q (rope applied in place)
__device__ float g_ckv [T_TOK * KVW];          // compressed kv + k_pe raw
__device__ float g_ckvn[T_TOK * KVLORA];       // rmsnormed compressed kv
__device__ float g_kpe [T_TOK * ROPE_D];       // rotated k_pe (shared across heads)
__device__ float g_kv  [T_TOK * NHEADS * 256]; // k_nope(128) + v(128) per head
__device__ float g_ctx [T_TOK * NHEADS * VHD]; // attention output context

// ---------------- GEMM: C(MxN) = A(MxK) * B(NxK)^T, all row-major ----------------
// 128x128 block tile, BK=16, 256 threads, 8x8 per-thread register tile.
// Smem tiles stored [row][k] with pad 17 (odd stride -> conflict-free compute reads).
__global__ __launch_bounds__(256) void gemm_nt(const float* __restrict__ A,
                                               const float* __restrict__ B,
                                               float* __restrict__ C,
                                               int M, int N, int K) {
    __shared__ float As[128 * 17];
    __shared__ float Bs[128 * 17];
    const int tid = threadIdx.x;
    const int ty  = tid >> 4;       // 0..15
    const int tx  = tid & 15;       // 0..15
    const int m0  = blockIdx.y * 128;
    const int n0  = blockIdx.x * 128;

    float acc[8][8];
#pragma unroll
    for (int i = 0; i < 8; ++i)
#pragma unroll
        for (int j = 0; j < 8; ++j) acc[i][j] = 0.f;

    for (int k0 = 0; k0 < K; k0 += 16) {
#pragma unroll
        for (int it = 0; it < 2; ++it) {
            int idx = tid + it * 256;         // 0..511
            int row = idx >> 2;               // 0..127
            int c4  = (idx & 3) * 4;          // 0,4,8,12
            float4 av = *(const float4*)(A + (size_t)(m0 + row) * K + k0 + c4);
            As[row * 17 + c4 + 0] = av.x;
            As[row * 17 + c4 + 1] = av.y;
            As[row * 17 + c4 + 2] = av.z;
            As[row * 17 + c4 + 3] = av.w;
            float4 bv = make_float4(0.f, 0.f, 0.f, 0.f);
            if (n0 + row < N)
                bv = *(const float4*)(B + (size_t)(n0 + row) * K + k0 + c4);
            Bs[row * 17 + c4 + 0] = bv.x;
            Bs[row * 17 + c4 + 1] = bv.y;
            Bs[row * 17 + c4 + 2] = bv.z;
            Bs[row * 17 + c4 + 3] = bv.w;
        }
        __syncthreads();
#pragma unroll
        for (int k = 0; k < 16; ++k) {
            float ra[8], rb[8];
#pragma unroll
            for (int i = 0; i < 8; ++i) ra[i] = As[(ty + i * 16) * 17 + k];
#pragma unroll
            for (int j = 0; j < 8; ++j) rb[j] = Bs[(tx + j * 16) * 17 + k];
#pragma unroll
            for (int i = 0; i < 8; ++i)
#pragma unroll
                for (int j = 0; j < 8; ++j) acc[i][j] += ra[i] * rb[j];
        }
        __syncthreads();
    }
#pragma unroll
    for (int i = 0; i < 8; ++i) {
        int row = m0 + ty + i * 16;
#pragma unroll
        for (int j = 0; j < 8; ++j) {
            int col = n0 + tx + j * 16;
            if (col < N) C[(size_t)row * N + col] = acc[i][j];
        }
    }
}

// ---------------- RMSNorm (per row, weight multiplied) ----------------
__global__ void rmsnorm_kernel(const float* __restrict__ x, const float* __restrict__ w,
                               float* __restrict__ y, int D, int in_stride, int out_stride) {
    const int row = blockIdx.x;
    const float* xr = x + (size_t)row * in_stride;
    float* yr = y + (size_t)row * out_stride;
    float ss = 0.f;
    for (int d = threadIdx.x; d < D; d += blockDim.x) { float v = xr[d]; ss += v * v; }
    __shared__ float red[32];
#pragma unroll
    for (int o = 16; o; o >>= 1) ss += __shfl_xor_sync(0xffffffffu, ss, o);
    if ((threadIdx.x & 31) == 0) red[threadIdx.x >> 5] = ss;
    __syncthreads();
    if (threadIdx.x < 32) {
        float v = (threadIdx.x < (blockDim.x >> 5)) ? red[threadIdx.x] : 0.f;
#pragma unroll
        for (int o = 16; o; o >>= 1) v += __shfl_xor_sync(0xffffffffu, v, o);
        if (threadIdx.x == 0) red[0] = v;
    }
    __syncthreads();
    float scale = rsqrtf(red[0] / (float)D + 1e-6f);
    for (int d = threadIdx.x; d < D; d += blockDim.x) yr[d] = w[d] * xr[d] * scale;
}

// ---------------- YaRN cos/sin ----------------
// dim=64, base=1e4, factor=40; low=10, high=23 -> denom=13 (precomputed from ref formula).
// mscale ratio = 1 so no extra multiplier on cos/sin.
__device__ __forceinline__ void yarn_cs(int pos, int j, float& c, float& s) {
    float ex   = __expf(-(float)(2 * j) * (9.210340371976184f / 64.f)); // base^(-2j/64)
    float fi   = ex * 0.025f;                                          // extrapolated / 40
    float ramp = ((float)j - 10.f) * (1.f / 13.f);
    ramp = fminf(fmaxf(ramp, 0.f), 1.f);
    float invf = fi * ramp + ex * (1.f - ramp);
    float ang  = (float)pos * invf;
    c = cosf(ang);
    s = sinf(ang);
}

// k_pe: read raw (interleaved) from ckv[...,512:576], write rotated half-layout to g_kpe.
__global__ void rope_k_kernel(const float* __restrict__ ckv, const int* __restrict__ pos_ids,
                              float* __restrict__ kpe) {
    const int t = blockIdx.x;
    const int j = threadIdx.x;       // 0..31
    const int pos = pos_ids[t];
    const float* x = ckv + (size_t)t * KVW + KVLORA;
    float c, s; yarn_cs(pos, j, c, s);
    float x0 = x[2 * j], x1 = x[2 * j + 1];
    kpe[t * ROPE_D + j]      = x0 * c - x1 * s;
    kpe[t * ROPE_D + 32 + j] = x1 * c + x0 * s;
}

// q_pe: rotate dims [128,192) of each head in place.
__global__ void rope_q_kernel(float* __restrict__ q, const int* __restrict__ pos_ids) {
    const int t = blockIdx.x >> 4;
    const int h = blockIdx.x & 15;
    const int j = threadIdx.x;       // 0..31
    const int pos = pos_ids[t];
    float* x = q + (size_t)t * (NHEADS * QHD) + h * QHD + NOPE;
    float c, s; yarn_cs(pos, j, c, s);
    float x0 = x[2 * j], x1 = x[2 * j + 1];
    __syncwarp();
    x[j]      = x0 * c - x1 * s;
    x[32 + j] = x1 * c + x0 * s;
}

// ---------------- flash attention (causal, fp32, online softmax) ----------------
// grid (qtile=32, head=16, batch=2); 256 threads; BM=BN=64.
// smem: Qs 64x193, Ks 64x193, Vs 64x129, Ps 64x65  -> 148480 B
#define ATT_SMEM ((64 * 193 * 2 + 64 * 129 + 64 * 65) * 4)

__global__ __launch_bounds__(256) void flash_kernel(const float* __restrict__ q,
                                                    const float* __restrict__ kv,
                                                    const float* __restrict__ kpe,
                                                    float* __restrict__ ctx) {
    extern __shared__ float sm[];
    float* Qs = sm;                   // [64][193]
    float* Ks = Qs + 64 * 193;        // [64][193]
    float* Vs = Ks + 64 * 193;        // [64][129]
    float* Ps = Vs + 64 * 129;        // [64][65]

    const int qt = blockIdx.x, h = blockIdx.y, b = blockIdx.z;
    const int tid = threadIdx.x, ty = tid >> 4, tx = tid & 15;
    const int t0 = b * S_LEN;

    for (int idx = tid; idx < 64 * QHD; idx += 256) {
        int r = idx / QHD, c2 = idx % QHD;
        Qs[r * 193 + c2] = q[(size_t)(t0 + qt * 64 + r) * (NHEADS * QHD) + h * QHD + c2];
    }

    float m_i[4], l_i[4], o[4][8];
#pragma unroll
    for (int i = 0; i < 4; ++i) {
        m_i[i] = -1e30f; l_i[i] = 0.f;
#pragma unroll
        for (int j = 0; j < 8; ++j) o[i][j] = 0.f;
    }
    const float mm = 0.1f * logf(40.f) + 1.f;
    const float sc = mm * mm * rsqrtf(192.f);
    __syncthreads();

    for (int kt = 0; kt <= qt; ++kt) {
        for (int idx = tid; idx < 64 * QHD; idx += 256) {
            int r = idx / QHD, c2 = idx % QHD;
            int t = t0 + kt * 64 + r;
            Ks[r * 193 + c2] = (c2 < NOPE) ? kv[(size_t)t * 4096 + h * 256 + c2]
                                           : kpe[t * ROPE_D + (c2 - NOPE)];
        }
        for (int idx = tid; idx < 64 * VHD; idx += 256) {
            int r = idx >> 7, c2 = idx & 127;
            Vs[r * 129 + c2] = kv[(size_t)(t0 + kt * 64 + r) * 4096 + h * 256 + 128 + c2];
        }
        __syncthreads();

        float sacc[4][4];
#pragma unroll
        for (int i = 0; i < 4; ++i)
#pragma unroll
            for (int j = 0; j < 4; ++j) sacc[i][j] = 0.f;

        for (int k = 0; k < QHD; ++k) {
            float ra[4], rb[4];
#pragma unroll
            for (int i = 0; i < 4; ++i) ra[i] = Qs[(ty + i * 16) * 193 + k];
#pragma unroll
            for (int j = 0; j < 4; ++j) rb[j] = Ks[(tx + j * 16) * 193 + k];
#pragma unroll
            for (int i = 0; i < 4; ++i)
#pragma unroll
                for (int j = 0; j < 4; ++j) sacc[i][j] += ra[i] * rb[j];
        }

#pragma unroll
        for (int i = 0; i < 4; ++i) {
            int row = qt * 64 + ty + i * 16;
            float tmax = -1e30f;
#pragma unroll
            for (int j = 0; j < 4; ++j) {
                int col = kt * 64 + tx + j * 16;
                float v = sacc[i][j] * sc;
                if (col > row) v = -1e30f;
                sacc[i][j] = v;
                tmax = fmaxf(tmax, v);
            }
#pragma unroll
            for (int off = 8; off; off >>= 1)
                tmax = fmaxf(tmax, __shfl_xor_sync(0xffffffffu, tmax, off));
            float nm  = fmaxf(m_i[i], tmax);
            float fac = __expf(m_i[i] - nm);
            float psum = 0.f;
#pragma unroll
            for (int j = 0; j < 4; ++j) {
                float p = __expf(sacc[i][j] - nm);
                sacc[i][j] = p;
                psum += p;
            }
#pragma unroll
            for (int off = 8; off; off >>= 1)
                psum += __shfl_xor_sync(0xffffffffu, psum, off);
            l_i[i] = l_i[i] * fac + psum;
            m_i[i] = nm;
#pragma unroll
            for (int j = 0; j < 8; ++j) o[i][j] *= fac;
#pragma unroll
            for (int j = 0; j < 4; ++j)
                Ps[(ty + i * 16) * 65 + tx + j * 16] = sacc[i][j];
        }
        __syncthreads();

        for (int kk = 0; kk < 64; ++kk) {
            float pv[4], vv[8];
#pragma unroll
            for (int i = 0; i < 4; ++i) pv[i] = Ps[(ty + i * 16) * 65 + kk];
#pragma unroll
            for (int j = 0; j < 8; ++j) vv[j] = Vs[kk * 129 + tx + j * 16];
#pragma unroll
            for (int i = 0; i < 4; ++i)
#pragma unroll
                for (int j = 0; j < 8; ++j) o[i][j] += pv[i] * vv[j];
        }
        __syncthreads();
    }

#pragma unroll
    for (int i = 0; i < 4; ++i) {
        float inv = 1.f / l_i[i];
#pragma unroll
        for (int j = 0; j < 8; ++j)
            ctx[(size_t)(t0 + qt * 64 + ty + i * 16) * (NHEADS * VHD) + h * VHD + tx + j * 16] =
                o[i][j] * inv;
    }
}

// ---------------- launch ----------------
extern "C" void kernel_launch(void* const* d_in, const int* in_sizes, int n_in,
                              void* d_out, int out_size) {
    (void)in_sizes; (void)n_in; (void)out_size;
    const float* X     = (const float*)d_in[0];
    const int*   pos   = (const int*)  d_in[1];
    const float* wq_a  = (const float*)d_in[2];
    const float* qln   = (const float*)d_in[3];
    const float* wq_b  = (const float*)d_in[4];
    const float* wkv_a = (const float*)d_in[5];
    const float* kvln  = (const float*)d_in[6];
    const float* wkv_b = (const float*)d_in[7];
    const float* wo    = (const float*)d_in[8];
    float* out = (float*)d_out;

    float *qa, *q, *ckv, *ckvn, *kpe, *kv, *ctx;
    cudaGetSymbolAddress((void**)&qa,   g_qa);
    cudaGetSymbolAddress((void**)&q,    g_q);
    cudaGetSymbolAddress((void**)&ckv,  g_ckv);
    cudaGetSymbolAddress((void**)&ckvn, g_ckvn);
    cudaGetSymbolAddress((void**)&kpe,  g_kpe);
    cudaGetSymbolAddress((void**)&kv,   g_kv);
    cudaGetSymbolAddress((void**)&ctx,  g_ctx);

    const dim3 blk(256);
    const int mt = T_TOK / 128;  // 32

    // q path
    gemm_nt<<<dim3(QLORA / 128, mt), blk>>>(X, wq_a, qa, T_TOK, QLORA, HIDDEN);
    rmsnorm_kernel<<<T_TOK, 256>>>(qa, qln, qa, QLORA, QLORA, QLORA);
    gemm_nt<<<dim3((NHEADS * QHD) / 128, mt), blk>>>(qa, wq_b, q, T_TOK, NHEADS * QHD, QLORA);

    // kv path
    gemm_nt<<<dim3((KVW + 127) / 128, mt), blk>>>(X, wkv_a, ckv, T_TOK, KVW, HIDDEN);
    rmsnorm_kernel<<<T_TOK, 256>>>(ckv, kvln, ckvn, KVLORA, KVW, KVLORA);
    rope_k_kernel<<<T_TOK, 32>>>(ckv, pos, kpe);
    gemm_nt<<<dim3((NHEADS * 256) / 128, mt), blk>>>(ckvn, wkv_b, kv, T_TOK, NHEADS * 256, KVLORA);

    // rope on q_pe
    rope_q_kernel<<<T_TOK * NHEADS, 32>>>(q, pos);

    // attention
    cudaFuncSetAttribute(flash_kernel, cudaFuncAttributeMaxDynamicSharedMemorySize, ATT_SMEM);
    flash_kernel<<<dim3(S_LEN / 64, NHEADS, BATCH), 256, ATT_SMEM>>>(q, kv, kpe, ctx);

    // output projection
    gemm_nt<<<dim3(HIDDEN / 128, mt), blk>>>(ctx, wo, out, T_TOK, HIDDEN, NHEADS * VHD);
}

// round 3
// speedup vs baseline: 1.4266x; 1.4266x over previous
#include <cuda_runtime.h>
#include <cuda_bf16.h>
#include <math.h>
#include <stdint.h>

// ---------------- problem constants ----------------
#define S_LEN   2048
#define BATCH   2
#define T_TOK   (BATCH * S_LEN)     // 4096 tokens
#define HIDDEN  2048
#define QLORA   1536
#define KVLORA  512
#define NHEADS  16
#define NOPE    128
#define ROPE_D  64
#define QHD     192
#define VHD     128
#define KVW     576

// ---------------- scratch ----------------
__device__ float g_qa  [T_TOK * QLORA];
__device__ float g_q   [T_TOK * NHEADS * QHD];
__device__ float g_ckv [T_TOK * KVW];
__device__ float g_ckvn[T_TOK * KVLORA];
__device__ float g_kpe [T_TOK * ROPE_D];
__device__ float g_kv  [T_TOK * NHEADS * 256];
__device__ float g_ctx [T_TOK * NHEADS * VHD];

// ============================================================================
// HMMA (mma.sync) split-bf16 GEMM: C(MxN) = A(MxK)*B(NxK)^T fp32 in/out.
// C = Ah*Bh + Ah*Bl + Al*Bh. 128x128 CTA tile, 8 warps (64x32 each), BK=32.
// ============================================================================
#define SMSTR  80                    // smem row stride in bytes (32 bf16 + 8 pad)
#define TILEB  (128 * SMSTR)         // 10240 B per tile
#define STAGEB (4 * TILEB)           // Ah, Al, Bh, Bl
#define GEMM_SMEM (2 * STAGEB)       // 81920 B double-buffered

__device__ __forceinline__ uint32_t smem_u32(const void* p) {
    uint32_t a;
    asm("{ .reg .u64 t; cvta.to.shared.u64 t, %1; cvt.u32.u64 %0, t; }" : "=r"(a) : "l"(p));
    return a;
}
__device__ __forceinline__ void ldm4(uint32_t* r, uint32_t addr) {
    asm volatile("ldmatrix.sync.aligned.m8n8.x4.shared.b16 {%0,%1,%2,%3}, [%4];"
                 : "=r"(r[0]), "=r"(r[1]), "=r"(r[2]), "=r"(r[3]) : "r"(addr));
}
__device__ __forceinline__ void mma16816(float* d, const uint32_t* a, const uint32_t* b) {
    asm volatile("mma.sync.aligned.m16n8k16.row.col.f32.bf16.bf16.f32 "
                 "{%0,%1,%2,%3}, {%4,%5,%6,%7}, {%8,%9}, {%0,%1,%2,%3};"
                 : "+f"(d[0]), "+f"(d[1]), "+f"(d[2]), "+f"(d[3])
                 : "r"(a[0]), "r"(a[1]), "r"(a[2]), "r"(a[3]), "r"(b[0]), "r"(b[1]));
}
// split a float4 into hi/lo bf16x4 packs
__device__ __forceinline__ void split4(float4 v, uint2& hp, uint2& lp) {
    __nv_bfloat162 h0 = __float22bfloat162_rn(make_float2(v.x, v.y));
    __nv_bfloat162 h1 = __float22bfloat162_rn(make_float2(v.z, v.w));
    float lx = v.x - __bfloat162float(h0.x);
    float ly = v.y - __bfloat162float(h0.y);
    float lz = v.z - __bfloat162float(h1.x);
    float lw = v.w - __bfloat162float(h1.y);
    __nv_bfloat162 l0 = __float22bfloat162_rn(make_float2(lx, ly));
    __nv_bfloat162 l1 = __float22bfloat162_rn(make_float2(lz, lw));
    hp.x = *(uint32_t*)&h0; hp.y = *(uint32_t*)&h1;
    lp.x = *(uint32_t*)&l0; lp.y = *(uint32_t*)&l1;
}

__global__ __launch_bounds__(256) void hmma_gemm(const float* __restrict__ A,
                                                 const float* __restrict__ B,
                                                 float* __restrict__ C,
                                                 int M, int N, int K) {
    extern __shared__ char sm[];
    const int tid = threadIdx.x;
    const int wid = tid >> 5;
    const int lane = tid & 31;
    const int m0 = blockIdx.y * 128;
    const int n0 = blockIdx.x * 128;
    const int nvalid = (N - n0 < 128) ? (N - n0) : 128;

    // per-thread load mapping: row = tid>>1, float col base = (tid&1)*16
    const int lr = tid >> 1;
    const int lc = (tid & 1) * 16;
    const float* aptr = A + (size_t)(m0 + lr) * K + lc;
    const float* bptr = B + (size_t)(n0 + lr) * K + lc;
    const bool bok = (lr < nvalid);
    const uint32_t so = (uint32_t)(lr * SMSTR + lc * 2);   // smem byte offset

    // warp tiling: 2x4 warps; warp tile 64x32
    const int wr = wid >> 2, wc = wid & 3;
    const uint32_t sbase = smem_u32(sm);
    const uint32_t a_row = wr * 64 + (lane & 15);
    const uint32_t a_col = (lane >> 4) * 16;
    const uint32_t b_row = wc * 32 + (lane & 7) + (lane >> 4) * 8;
    const uint32_t b_col = ((lane >> 3) & 1) * 16;

    float acc[4][4][4];
#pragma unroll
    for (int i = 0; i < 4; ++i)
#pragma unroll
        for (int j = 0; j < 4; ++j)
#pragma unroll
            for (int e = 0; e < 4; ++e) acc[i][j][e] = 0.f;

    const int nch = K >> 5;

    // ---- preload chunk 0 into stage 0 ----
    {
        char* st = sm;
#pragma unroll
        for (int i = 0; i < 4; ++i) {
            float4 va = *(const float4*)(aptr + i * 4);
            float4 vb = bok ? *(const float4*)(bptr + i * 4) : make_float4(0.f, 0.f, 0.f, 0.f);
            uint2 hp, lp;
            split4(va, hp, lp);
            *(uint2*)(st + so + i * 8) = hp;
            *(uint2*)(st + TILEB + so + i * 8) = lp;
            split4(vb, hp, lp);
            *(uint2*)(st + 2 * TILEB + so + i * 8) = hp;
            *(uint2*)(st + 3 * TILEB + so + i * 8) = lp;
        }
    }
    __syncthreads();

    for (int c = 0; c < nch; ++c) {
        // prefetch next chunk to registers (LDG latency overlaps MMA below)
        float4 pva[4], pvb[4];
        if (c + 1 < nch) {
            const float* ap = aptr + (c + 1) * 32;
            const float* bp = bptr + (c + 1) * 32;
#pragma unroll
            for (int i = 0; i < 4; ++i) {
                pva[i] = *(const float4*)(ap + i * 4);
                pvb[i] = bok ? *(const float4*)(bp + i * 4) : make_float4(0.f, 0.f, 0.f, 0.f);
            }
        }

        // compute from stage c&1
        const uint32_t stb = sbase + (c & 1) * STAGEB;
#pragma unroll
        for (int ks = 0; ks < 2; ++ks) {
            const uint32_t kb = ks * 32;
            uint32_t ah[4][4], al[4][4], bh[2][4], bl[2][4];
#pragma unroll
            for (int i = 0; i < 4; ++i) {
                uint32_t ad = stb + (a_row + i * 16) * SMSTR + a_col + kb;
                ldm4(ah[i], ad);
                ldm4(al[i], ad + TILEB);
            }
#pragma unroll
            for (int jp = 0; jp < 2; ++jp) {
                uint32_t bd = stb + 2 * TILEB + (b_row + jp * 16) * SMSTR + b_col + kb;
                ldm4(bh[jp], bd);
                ldm4(bl[jp], bd + TILEB);
            }
#pragma unroll
            for (int i = 0; i < 4; ++i)
#pragma unroll
                for (int j = 0; j < 4; ++j) {
                    const uint32_t* ph = &bh[j >> 1][(j & 1) * 2];
                    const uint32_t* pl = &bl[j >> 1][(j & 1) * 2];
                    mma16816(acc[i][j], ah[i], ph);
                    mma16816(acc[i][j], ah[i], pl);
                    mma16816(acc[i][j], al[i], ph);
                }
        }

        // store next chunk into the other stage
        if (c + 1 < nch) {
            char* st = sm + ((c + 1) & 1) * STAGEB;
#pragma unroll
            for (int i = 0; i < 4; ++i) {
                uint2 hp, lp;
                split4(pva[i], hp, lp);
                *(uint2*)(st + so + i * 8) = hp;
                *(uint2*)(st + TILEB + so + i * 8) = lp;
                split4(pvb[i], hp, lp);
                *(uint2*)(st + 2 * TILEB + so + i * 8) = hp;
                *(uint2*)(st + 3 * TILEB + so + i * 8) = lp;
            }
        }
        __syncthreads();
    }

    // epilogue
    const int gid = lane >> 2, tig = lane & 3;
#pragma unroll
    for (int i = 0; i < 4; ++i) {
        int row = m0 + wr * 64 + i * 16 + gid;
#pragma unroll
        for (int j = 0; j < 4; ++j) {
            int col = n0 + wc * 32 + j * 8 + tig * 2;
            if (col < N) {
                *(float2*)(C + (size_t)row * N + col) = make_float2(acc[i][j][0], acc[i][j][1]);
                *(float2*)(C + (size_t)(row + 8) * N + col) = make_float2(acc[i][j][2], acc[i][j][3]);
            }
        }
    }
}

// ---------------- RMSNorm ----------------
__global__ void rmsnorm_kernel(const float* __restrict__ x, const float* __restrict__ w,
                               float* __restrict__ y, int D, int in_stride, int out_stride) {
    const int row = blockIdx.x;
    const float* xr = x + (size_t)row * in_stride;
    float* yr = y + (size_t)row * out_stride;
    float ss = 0.f;
    for (int d = threadIdx.x; d < D; d += blockDim.x) { float v = xr[d]; ss += v * v; }
    __shared__ float red[32];
#pragma unroll
    for (int o = 16; o; o >>= 1) ss += __shfl_xor_sync(0xffffffffu, ss, o);
    if ((threadIdx.x & 31) == 0) red[threadIdx.x >> 5] = ss;
    __syncthreads();
    if (threadIdx.x < 32) {
        float v = (threadIdx.x < (blockDim.x >> 5)) ? red[threadIdx.x] : 0.f;
#pragma unroll
        for (int o = 16; o; o >>= 1) v += __shfl_xor_sync(0xffffffffu, v, o);
        if (threadIdx.x == 0) red[0] = v;
    }
    __syncthreads();
    float scale = rsqrtf(red[0] / (float)D + 1e-6f);
    for (int d = threadIdx.x; d < D; d += blockDim.x) yr[d] = w[d] * xr[d] * scale;
}

// ---------------- YaRN cos/sin ----------------
__device__ __forceinline__ void yarn_cs(int pos, int j, float& c, float& s) {
    float ex   = __expf(-(float)(2 * j) * (9.210340371976184f / 64.f));
    float fi   = ex * 0.025f;
    float ramp = ((float)j - 10.f) * (1.f / 13.f);
    ramp = fminf(fmaxf(ramp, 0.f), 1.f);
    float invf = fi * ramp + ex * (1.f - ramp);
    float ang  = (float)pos * invf;
    c = cosf(ang);
    s = sinf(ang);
}

__global__ void rope_k_kernel(const float* __restrict__ ckv, const int* __restrict__ pos_ids,
                              float* __restrict__ kpe) {
    const int t = blockIdx.x;
    const int j = threadIdx.x;
    const int pos = pos_ids[t];
    const float* x = ckv + (size_t)t * KVW + KVLORA;
    float c, s; yarn_cs(pos, j, c, s);
    float x0 = x[2 * j], x1 = x[2 * j + 1];
    kpe[t * ROPE_D + j]      = x0 * c - x1 * s;
    kpe[t * ROPE_D + 32 + j] = x1 * c + x0 * s;
}

__global__ void rope_q_kernel(float* __restrict__ q, const int* __restrict__ pos_ids) {
    const int t = blockIdx.x >> 4;
    const int h = blockIdx.x & 15;
    const int j = threadIdx.x;
    const int pos = pos_ids[t];
    float* x = q + (size_t)t * (NHEADS * QHD) + h * QHD + NOPE;
    float c, s; yarn_cs(pos, j, c, s);
    float x0 = x[2 * j], x1 = x[2 * j + 1];
    __syncwarp();
    x[j]      = x0 * c - x1 * s;
    x[32 + j] = x1 * c + x0 * s;
}

// ---------------- flash attention (causal, fp32, online softmax) ----------------
#define ATT_SMEM ((64 * 193 * 2 + 64 * 129 + 64 * 65) * 4)

__global__ __launch_bounds__(256) void flash_kernel(const float* __restrict__ q,
                                                    const float* __restrict__ kv,
                                                    const float* __restrict__ kpe,
                                                    float* __restrict__ ctx) {
    extern __shared__ float smf[];
    float* Qs = smf;
    float* Ks = Qs + 64 * 193;
    float* Vs = Ks + 64 * 193;
    float* Ps = Vs + 64 * 129;

    const int qt = blockIdx.x, h = blockIdx.y, b = blockIdx.z;
    const int tid = threadIdx.x, ty = tid >> 4, tx = tid & 15;
    const int t0 = b * S_LEN;

    for (int idx = tid; idx < 64 * QHD; idx += 256) {
        int r = idx / QHD, c2 = idx % QHD;
        Qs[r * 193 + c2] = q[(size_t)(t0 + qt * 64 + r) * (NHEADS * QHD) + h * QHD + c2];
    }

    float m_i[4], l_i[4], o[4][8];
#pragma unroll
    for (int i = 0; i < 4; ++i) {
        m_i[i] = -1e30f; l_i[i] = 0.f;
#pragma unroll
        for (int j = 0; j < 8; ++j) o[i][j] = 0.f;
    }
    const float mm = 0.1f * logf(40.f) + 1.f;
    const float sc = mm * mm * rsqrtf(192.f);
    __syncthreads();

    for (int kt = 0; kt <= qt; ++kt) {
        for (int idx = tid; idx < 64 * QHD; idx += 256) {
            int r = idx / QHD, c2 = idx % QHD;
            int t = t0 + kt * 64 + r;
            Ks[r * 193 + c2] = (c2 < NOPE) ? kv[(size_t)t * 4096 + h * 256 + c2]
                                           : kpe[t * ROPE_D + (c2 - NOPE)];
        }
        for (int idx = tid; idx < 64 * VHD; idx += 256) {
            int r = idx >> 7, c2 = idx & 127;
            Vs[r * 129 + c2] = kv[(size_t)(t0 + kt * 64 + r) * 4096 + h * 256 + 128 + c2];
        }
        __syncthreads();

        float sacc[4][4];
#pragma unroll
        for (int i = 0; i < 4; ++i)
#pragma unroll
            for (int j = 0; j < 4; ++j) sacc[i][j] = 0.f;

        for (int k = 0; k < QHD; ++k) {
            float ra[4], rb[4];
#pragma unroll
            for (int i = 0; i < 4; ++i) ra[i] = Qs[(ty + i * 16) * 193 + k];
#pragma unroll
            for (int j = 0; j < 4; ++j) rb[j] = Ks[(tx + j * 16) * 193 + k];
#pragma unroll
            for (int i = 0; i < 4; ++i)
#pragma unroll
                for (int j = 0; j < 4; ++j) sacc[i][j] += ra[i] * rb[j];
        }

#pragma unroll
        for (int i = 0; i < 4; ++i) {
            int row = qt * 64 + ty + i * 16;
            float tmax = -1e30f;
#pragma unroll
            for (int j = 0; j < 4; ++j) {
                int col = kt * 64 + tx + j * 16;
                float v = sacc[i][j] * sc;
                if (col > row) v = -1e30f;
                sacc[i][j] = v;
                tmax = fmaxf(tmax, v);
            }
#pragma unroll
            for (int off = 8; off; off >>= 1)
                tmax = fmaxf(tmax, __shfl_xor_sync(0xffffffffu, tmax, off));
            float nm  = fmaxf(m_i[i], tmax);
            float fac = __expf(m_i[i] - nm);
            float psum = 0.f;
#pragma unroll
            for (int j = 0; j < 4; ++j) {
                float p = __expf(sacc[i][j] - nm);
                sacc[i][j] = p;
                psum += p;
            }
#pragma unroll
            for (int off = 8; off; off >>= 1)
                psum += __shfl_xor_sync(0xffffffffu, psum, off);
            l_i[i] = l_i[i] * fac + psum;
            m_i[i] = nm;
#pragma unroll
            for (int j = 0; j < 8; ++j) o[i][j] *= fac;
#pragma unroll
            for (int j = 0; j < 4; ++j)
                Ps[(ty + i * 16) * 65 + tx + j * 16] = sacc[i][j];
        }
        __syncthreads();

        for (int kk = 0; kk < 64; ++kk) {
            float pv[4], vv[8];
#pragma unroll
            for (int i = 0; i < 4; ++i) pv[i] = Ps[(ty + i * 16) * 65 + kk];
#pragma unroll
            for (int j = 0; j < 8; ++j) vv[j] = Vs[kk * 129 + tx + j * 16];
#pragma unroll
            for (int i = 0; i < 4; ++i)
#pragma unroll
                for (int j = 0; j < 8; ++j) o[i][j] += pv[i] * vv[j];
        }
        __syncthreads();
    }

#pragma unroll
    for (int i = 0; i < 4; ++i) {
        float inv = 1.f / l_i[i];
#pragma unroll
        for (int j = 0; j < 8; ++j)
            ctx[(size_t)(t0 + qt * 64 + ty + i * 16) * (NHEADS * VHD) + h * VHD + tx + j * 16] =
                o[i][j] * inv;
    }
}

// ---------------- launch ----------------
extern "C" void kernel_launch(void* const* d_in, const int* in_sizes, int n_in,
                              void* d_out, int out_size) {
    (void)in_sizes; (void)n_in; (void)out_size;
    const float* X     = (const float*)d_in[0];
    const int*   pos   = (const int*)  d_in[1];
    const float* wq_a  = (const float*)d_in[2];
    const float* qln   = (const float*)d_in[3];
    const float* wq_b  = (const float*)d_in[4];
    const float* wkv_a = (const float*)d_in[5];
    const float* kvln  = (const float*)d_in[6];
    const float* wkv_b = (const float*)d_in[7];
    const float* wo    = (const float*)d_in[8];
    float* out = (float*)d_out;

    float *qa, *q, *ckv, *ckvn, *kpe, *kv, *ctx;
    cudaGetSymbolAddress((void**)&qa,   g_qa);
    cudaGetSymbolAddress((void**)&q,    g_q);
    cudaGetSymbolAddress((void**)&ckv,  g_ckv);
    cudaGetSymbolAddress((void**)&ckvn, g_ckvn);
    cudaGetSymbolAddress((void**)&kpe,  g_kpe);
    cudaGetSymbolAddress((void**)&kv,   g_kv);
    cudaGetSymbolAddress((void**)&ctx,  g_ctx);

    cudaFuncSetAttribute(hmma_gemm, cudaFuncAttributeMaxDynamicSharedMemorySize, GEMM_SMEM);
    cudaFuncSetAttribute(flash_kernel, cudaFuncAttributeMaxDynamicSharedMemorySize, ATT_SMEM);

    const dim3 blk(256);
    const int mt = T_TOK / 128;  // 32

    // q path
    hmma_gemm<<<dim3(QLORA / 128, mt), blk, GEMM_SMEM>>>(X, wq_a, qa, T_TOK, QLORA, HIDDEN);
    rmsnorm_kernel<<<T_TOK, 256>>>(qa, qln, qa, QLORA, QLORA, QLORA);
    hmma_gemm<<<dim3((NHEADS * QHD) / 128, mt), blk, GEMM_SMEM>>>(qa, wq_b, q, T_TOK, NHEADS * QHD, QLORA);

    // kv path
    hmma_gemm<<<dim3((KVW + 127) / 128, mt), blk, GEMM_SMEM>>>(X, wkv_a, ckv, T_TOK, KVW, HIDDEN);
    rmsnorm_kernel<<<T_TOK, 256>>>(ckv, kvln, ckvn, KVLORA, KVW, KVLORA);
    rope_k_kernel<<<T_TOK, 32>>>(ckv, pos, kpe);
    hmma_gemm<<<dim3((NHEADS * 256) / 128, mt), blk, GEMM_SMEM>>>(ckvn, wkv_b, kv, T_TOK, NHEADS * 256, KVLORA);

    // rope on q_pe
    rope_q_kernel<<<T_TOK * NHEADS, 32>>>(q, pos);

    // attention
    flash_kernel<<<dim3(S_LEN / 64, NHEADS, BATCH), 256, ATT_SMEM>>>(q, kv, kpe, ctx);

    // output projection
    hmma_gemm<<<dim3(HIDDEN / 128, mt), blk, GEMM_SMEM>>>(ctx, wo, out, T_TOK, HIDDEN, NHEADS * VHD);
}

// round 4
// speedup vs baseline: 3.3864x; 2.3738x over previous
#include <cuda_runtime.h>
#include <cuda_bf16.h>
#include <math.h>
#include <stdint.h>

// ---------------- problem constants ----------------
#define S_LEN   2048
#define BATCH   2
#define T_TOK   (BATCH * S_LEN)
#define HIDDEN  2048
#define QLORA   1536
#define KVLORA  512
#define NHEADS  16
#define NOPE    128
#define ROPE_D  64
#define QHD     192
#define VHD     128
#define KVW     576

typedef __nv_bfloat16 bf16;
typedef __nv_bfloat162 bf162;

// ---------------- scratch ----------------
__device__ float g_qa [T_TOK * QLORA];
__device__ float g_ckv[T_TOK * KVW];

__device__ bf16 g_Xh[T_TOK * HIDDEN],       g_Xl[T_TOK * HIDDEN];
__device__ bf16 g_wqa_h[QLORA * HIDDEN],    g_wqa_l[QLORA * HIDDEN];
__device__ bf16 g_wqb_h[NHEADS*QHD*QLORA],  g_wqb_l[NHEADS*QHD*QLORA];
__device__ bf16 g_wkva_h[KVW * HIDDEN],     g_wkva_l[KVW * HIDDEN];
__device__ bf16 g_wkvb_h[NHEADS*256*KVLORA],g_wkvb_l[NHEADS*256*KVLORA];
__device__ bf16 g_wo_h[HIDDEN*NHEADS*VHD],  g_wo_l[HIDDEN*NHEADS*VHD];
__device__ bf16 g_qan_h[T_TOK * QLORA],     g_qan_l[T_TOK * QLORA];
__device__ bf16 g_ckvn_h[T_TOK * KVLORA],   g_ckvn_l[T_TOK * KVLORA];
__device__ bf16 g_qh[T_TOK * NHEADS * QHD], g_ql[T_TOK * NHEADS * QHD];
__device__ bf16 g_kvh[T_TOK * NHEADS * 256],g_kvl[T_TOK * NHEADS * 256];
__device__ bf16 g_kpeh[T_TOK * ROPE_D],     g_kpel[T_TOK * ROPE_D];
__device__ bf16 g_ctxh[T_TOK * NHEADS*VHD], g_ctxl[T_TOK * NHEADS*VHD];

// ---------------- common helpers ----------------
__device__ __forceinline__ uint32_t smem_u32(const void* p) {
    uint32_t a;
    asm("{ .reg .u64 t; cvta.to.shared.u64 t, %1; cvt.u32.u64 %0, t; }" : "=r"(a) : "l"(p));
    return a;
}
__device__ __forceinline__ void ldm4(uint32_t* r, uint32_t addr) {
    asm volatile("ldmatrix.sync.aligned.m8n8.x4.shared.b16 {%0,%1,%2,%3}, [%4];"
                 : "=r"(r[0]), "=r"(r[1]), "=r"(r[2]), "=r"(r[3]) : "r"(addr));
}
__device__ __forceinline__ void ldm4t(uint32_t* r, uint32_t addr) {
    asm volatile("ldmatrix.sync.aligned.m8n8.x4.trans.shared.b16 {%0,%1,%2,%3}, [%4];"
                 : "=r"(r[0]), "=r"(r[1]), "=r"(r[2]), "=r"(r[3]) : "r"(addr));
}
__device__ __forceinline__ void mma16816(float* d, const uint32_t* a, const uint32_t* b) {
    asm volatile("mma.sync.aligned.m16n8k16.row.col.f32.bf16.bf16.f32 "
                 "{%0,%1,%2,%3}, {%4,%5,%6,%7}, {%8,%9}, {%0,%1,%2,%3};"
                 : "+f"(d[0]), "+f"(d[1]), "+f"(d[2]), "+f"(d[3])
                 : "r"(a[0]), "r"(a[1]), "r"(a[2]), "r"(a[3]), "r"(b[0]), "r"(b[1]));
}
__device__ __forceinline__ void cpa16(uint32_t dst, const void* src, uint32_t sz) {
    asm volatile("cp.async.ca.shared.global [%0], [%1], 16, %2;"
                 :: "r"(dst), "l"(src), "r"(sz) : "memory");
}
__device__ __forceinline__ void split1(float v, bf16& h, bf16& l) {
    h = __float2bfloat16_rn(v);
    l = __float2bfloat16_rn(v - __bfloat162float(h));
}

// ---------------- convert fp32 -> (hi, lo) bf16 ----------------
__global__ void cvt_kernel(const float* __restrict__ x, bf16* __restrict__ h,
                           bf16* __restrict__ l, int n4) {
    int i = blockIdx.x * blockDim.x + threadIdx.x;
    if (i >= n4) return;
    float4 v = ((const float4*)x)[i];
    bf16 h0,h1,h2,h3,l0,l1,l2,l3;
    split1(v.x,h0,l0); split1(v.y,h1,l1); split1(v.z,h2,l2); split1(v.w,h3,l3);
    bf162 hp0, hp1, lp0, lp1;
    hp0.x=h0; hp0.y=h1; hp1.x=h2; hp1.y=h3;
    lp0.x=l0; lp0.y=l1; lp1.x=l2; lp1.y=l3;
    uint2 hh, ll;
    hh.x=*(uint32_t*)&hp0; hh.y=*(uint32_t*)&hp1;
    ll.x=*(uint32_t*)&lp0; ll.y=*(uint32_t*)&lp1;
    ((uint2*)h)[i] = hh;
    ((uint2*)l)[i] = ll;
}

// ============================================================================
// bf16 split GEMM: C = A*B^T. Inputs pre-split (Ah,Al,Bh,Bl bf16 K-major).
// 128x128 CTA tile, BK=32, 2-stage cp.async, 8 warps (64x32 warp tile).
// Optional fp32 C and/or bf16 hi/lo C outputs.
// ============================================================================
#define SMSTR 80
#define TILEB (128 * SMSTR)
#define STAGEB (4 * TILEB)
#define GEMM_SMEM (2 * STAGEB)

__global__ __launch_bounds__(256, 2) void bf_gemm(
    const bf16* __restrict__ Ah, const bf16* __restrict__ Al,
    const bf16* __restrict__ Bh, const bf16* __restrict__ Bl,
    float* __restrict__ C, bf16* __restrict__ Ch, bf16* __restrict__ Cl,
    int M, int N, int K)
{
    extern __shared__ char sm[];
    const int tid = threadIdx.x;
    const int wid = tid >> 5;
    const int lane = tid & 31;
    const int m0 = blockIdx.y * 128;
    const int n0 = blockIdx.x * 128;
    const int nvalid = (N - n0 < 128) ? (N - n0) : 128;

    const uint32_t sbase = smem_u32(sm);
    const int wr = wid >> 2, wc = wid & 3;
    const uint32_t a_row = wr * 64 + (lane & 15);
    const uint32_t a_colb = (lane >> 4) * 16;
    const uint32_t b_row = wc * 32 + (lane & 7) + ((lane >> 4) << 3);
    const uint32_t b_colb = ((lane >> 3) & 1) * 16;

    float acc[4][4][4];
#pragma unroll
    for (int i = 0; i < 4; ++i)
#pragma unroll
        for (int j = 0; j < 4; ++j)
#pragma unroll
            for (int e = 0; e < 4; ++e) acc[i][j][e] = 0.f;

    const int nch = K >> 5;

    // per-thread copy slots: 8 x 16B per chunk
    // unit u = tid + i*256 : tile=u>>9 (0:Ah 1:Al 2:Bh 3:Bl), row=(u&511)>>2, c16=u&3
    auto issue_chunk = [&](int c, int stage) {
        const int k0 = c << 5;
        const uint32_t stb = sbase + stage * STAGEB;
#pragma unroll
        for (int i = 0; i < 8; ++i) {
            int u = tid + i * 256;
            int tile = u >> 9;
            int row = (u & 511) >> 2;
            int c16 = u & 3;
            uint32_t dst = stb + tile * TILEB + row * SMSTR + c16 * 16;
            const bf16* src;
            uint32_t sz = 16;
            if (tile == 0)      src = Ah + (size_t)(m0 + row) * K + k0 + c16 * 8;
            else if (tile == 1) src = Al + (size_t)(m0 + row) * K + k0 + c16 * 8;
            else {
                const bf16* base = (tile == 2) ? Bh : Bl;
                src = base + (size_t)(n0 + row) * K + k0 + c16 * 8;
                if (row >= nvalid) sz = 0;
            }
            cpa16(dst, src, sz);
        }
        asm volatile("cp.async.commit_group;" ::: "memory");
    };

    issue_chunk(0, 0);

    for (int c = 0; c < nch; ++c) {
        if (c + 1 < nch) {
            issue_chunk(c + 1, (c + 1) & 1);
            asm volatile("cp.async.wait_group 1;" ::: "memory");
        } else {
            asm volatile("cp.async.wait_group 0;" ::: "memory");
        }
        __syncthreads();

        const uint32_t stb = sbase + (c & 1) * STAGEB;
#pragma unroll
        for (int ks = 0; ks < 2; ++ks) {
            const uint32_t kb = ks * 32;
            uint32_t ah[4][4], bh[2][4];
#pragma unroll
            for (int i = 0; i < 4; ++i)
                ldm4(ah[i], stb + (a_row + i * 16) * SMSTR + a_colb + kb);
#pragma unroll
            for (int jp = 0; jp < 2; ++jp)
                ldm4(bh[jp], stb + 2 * TILEB + (b_row + jp * 16) * SMSTR + b_colb + kb);
            // Ah*Bh
#pragma unroll
            for (int i = 0; i < 4; ++i)
#pragma unroll
                for (int j = 0; j < 4; ++j)
                    mma16816(acc[i][j], ah[i], &bh[j >> 1][(j & 1) * 2]);
            // Al*Bh
            {
                uint32_t al[4][4];
#pragma unroll
                for (int i = 0; i < 4; ++i)
                    ldm4(al[i], stb + TILEB + (a_row + i * 16) * SMSTR + a_colb + kb);
#pragma unroll
                for (int i = 0; i < 4; ++i)
#pragma unroll
                    for (int j = 0; j < 4; ++j)
                        mma16816(acc[i][j], al[i], &bh[j >> 1][(j & 1) * 2]);
            }
            // Ah*Bl
            {
                uint32_t bl[2][4];
#pragma unroll
                for (int jp = 0; jp < 2; ++jp)
                    ldm4(bl[jp], stb + 3 * TILEB + (b_row + jp * 16) * SMSTR + b_colb + kb);
#pragma unroll
                for (int i = 0; i < 4; ++i)
#pragma unroll
                    for (int j = 0; j < 4; ++j)
                        mma16816(acc[i][j], ah[i], &bl[j >> 1][(j & 1) * 2]);
            }
        }
        __syncthreads();
    }

    // epilogue
    const int gid = lane >> 2, tig = lane & 3;
#pragma unroll
    for (int i = 0; i < 4; ++i) {
#pragma unroll
        for (int rr = 0; rr < 2; ++rr) {
            int row = m0 + wr * 64 + i * 16 + gid + rr * 8;
#pragma unroll
            for (int j = 0; j < 4; ++j) {
                int col = n0 + wc * 32 + j * 8 + tig * 2;
                if (col < N) {
                    float v0 = acc[i][j][rr * 2], v1 = acc[i][j][rr * 2 + 1];
                    if (C) *(float2*)(C + (size_t)row * N + col) = make_float2(v0, v1);
                    if (Ch) {
                        bf162 hp, lp;
                        bf16 h0,l0,h1,l1;
                        split1(v0,h0,l0); split1(v1,h1,l1);
                        hp.x=h0; hp.y=h1; lp.x=l0; lp.y=l1;
                        *(uint32_t*)(Ch + (size_t)row * N + col) = *(uint32_t*)&hp;
                        *(uint32_t*)(Cl + (size_t)row * N + col) = *(uint32_t*)&lp;
                    }
                }
            }
        }
    }
}

// ---------------- RMSNorm -> bf16 hi/lo ----------------
__global__ void rmsnorm_kernel(const float* __restrict__ x, const float* __restrict__ w,
                               bf16* __restrict__ yh, bf16* __restrict__ yl,
                               int D, int in_stride) {
    const int row = blockIdx.x;
    const float* xr = x + (size_t)row * in_stride;
    float ss = 0.f;
    for (int d = threadIdx.x; d < D; d += blockDim.x) { float v = xr[d]; ss += v * v; }
    __shared__ float red[32];
#pragma unroll
    for (int o = 16; o; o >>= 1) ss += __shfl_xor_sync(0xffffffffu, ss, o);
    if ((threadIdx.x & 31) == 0) red[threadIdx.x >> 5] = ss;
    __syncthreads();
    if (threadIdx.x < 32) {
        float v = (threadIdx.x < (blockDim.x >> 5)) ? red[threadIdx.x] : 0.f;
#pragma unroll
        for (int o = 16; o; o >>= 1) v += __shfl_xor_sync(0xffffffffu, v, o);
        if (threadIdx.x == 0) red[0] = v;
    }
    __syncthreads();
    float scale = rsqrtf(red[0] / (float)D + 1e-6f);
    for (int d = threadIdx.x; d < D; d += blockDim.x) {
        float v = w[d] * xr[d] * scale;
        bf16 h, l; split1(v, h, l);
        yh[(size_t)row * D + d] = h;
        yl[(size_t)row * D + d] = l;
    }
}

// ---------------- YaRN ----------------
__device__ __forceinline__ void yarn_cs(int pos, int j, float& c, float& s) {
    float ex   = __expf(-(float)(2 * j) * (9.210340371976184f / 64.f));
    float fi   = ex * 0.025f;
    float ramp = ((float)j - 10.f) * (1.f / 13.f);
    ramp = fminf(fmaxf(ramp, 0.f), 1.f);
    float invf = fi * ramp + ex * (1.f - ramp);
    float ang  = (float)pos * invf;
    c = cosf(ang); s = sinf(ang);
}

__global__ void rope_k_kernel(const float* __restrict__ ckv, const int* __restrict__ pos_ids,
                              bf16* __restrict__ kh, bf16* __restrict__ kl) {
    const int t = blockIdx.x;
    const int j = threadIdx.x;
    const int pos = pos_ids[t];
    const float* x = ckv + (size_t)t * KVW + KVLORA;
    float c, s; yarn_cs(pos, j, c, s);
    float x0 = x[2 * j], x1 = x[2 * j + 1];
    float r0 = x0 * c - x1 * s, r1 = x1 * c + x0 * s;
    bf16 h, l;
    split1(r0, h, l); kh[t * ROPE_D + j] = h;      kl[t * ROPE_D + j] = l;
    split1(r1, h, l); kh[t * ROPE_D + 32 + j] = h; kl[t * ROPE_D + 32 + j] = l;
}

__global__ void rope_q_kernel(bf16* __restrict__ qh, bf16* __restrict__ ql,
                              const int* __restrict__ pos_ids) {
    const int t = blockIdx.x >> 4;
    const int h = blockIdx.x & 15;
    const int j = threadIdx.x;
    const int pos = pos_ids[t];
    bf16* xh = qh + (size_t)t * (NHEADS * QHD) + h * QHD + NOPE;
    bf16* xl = ql + (size_t)t * (NHEADS * QHD) + h * QHD + NOPE;
    float c, s; yarn_cs(pos, j, c, s);
    float x0 = __bfloat162float(xh[2*j])   + __bfloat162float(xl[2*j]);
    float x1 = __bfloat162float(xh[2*j+1]) + __bfloat162float(xl[2*j+1]);
    float r0 = x0 * c - x1 * s, r1 = x1 * c + x0 * s;
    __syncwarp();
    bf16 hh, ll;
    split1(r0, hh, ll); xh[j] = hh;      xl[j] = ll;
    split1(r1, hh, ll); xh[32 + j] = hh; xl[32 + j] = ll;
}

// ============================================================================
// Flash attention, split-bf16 HMMA. BM=128 q rows, BN=64 keys, 8 warps.
// Warp tile: 16 q rows x all 64 keys (QK) / x 128 vdims (AV).
// ============================================================================
#define FL_QSTR 400
#define FL_KSTR 400
#define FL_VSTR 272
#define FL_PSTR 144
#define FL_QH 0
#define FL_QL (FL_QH + 128 * FL_QSTR)          // 51200
#define FL_KH (FL_QL + 128 * FL_QSTR)          // 102400
#define FL_KL (FL_KH + 64 * FL_KSTR)           // 128000
#define FL_VH (FL_KL + 64 * FL_KSTR)           // 153600
#define FL_VL (FL_VH + 64 * FL_VSTR)           // 171008
#define FL_PH (FL_VL + 64 * FL_VSTR)           // 188416
#define FL_PL (FL_PH + 128 * FL_PSTR)          // 206848
#define FL_SMEM (FL_PL + 128 * FL_PSTR)        // 225280

__global__ __launch_bounds__(256, 1) void flash_mma(
    const bf16* __restrict__ qh, const bf16* __restrict__ ql,
    const bf16* __restrict__ kvh, const bf16* __restrict__ kvl,
    const bf16* __restrict__ kpeh, const bf16* __restrict__ kpel,
    bf16* __restrict__ ctxh, bf16* __restrict__ ctxl)
{
    extern __shared__ char sm[];
    const uint32_t sb = smem_u32(sm);
    const int qt = blockIdx.x, hh = blockIdx.y, b = blockIdx.z;
    const int tid = threadIdx.x, wid = tid >> 5, lane = tid & 31;
    const int gid = lane >> 2, tig = lane & 3;
    const int t0 = b * S_LEN;

    // ---- load Q tile (128 x 192, hi+lo) ----
    for (int idx = tid; idx < 128 * 24; idx += 256) {
        int r = idx / 24, u = idx % 24;
        size_t g = (size_t)(t0 + qt * 128 + r) * (NHEADS * QHD) + hh * QHD + u * 8;
        *(uint4*)(sm + FL_QH + r * FL_QSTR + u * 16) = *(const uint4*)(qh + g);
        *(uint4*)(sm + FL_QL + r * FL_QSTR + u * 16) = *(const uint4*)(ql + g);
    }

    float m_i[2], l_i[2], O[16][4];
    m_i[0] = m_i[1] = -1e30f; l_i[0] = l_i[1] = 0.f;
#pragma unroll
    for (int nf = 0; nf < 16; ++nf)
#pragma unroll
        for (int e = 0; e < 4; ++e) O[nf][e] = 0.f;

    const float mm = 0.1f * logf(40.f) + 1.f;
    const float sc = mm * mm * rsqrtf(192.f);

    // frag address components
    const uint32_t a_row = wid * 16 + (lane & 15);
    const uint32_t a_colb = (lane >> 4) * 16;
    const uint32_t k_roff = (lane & 7) + ((lane >> 4) << 3);
    const uint32_t k_colb = ((lane >> 3) & 1) * 16;
    const uint32_t v_koff = (lane & 7) + ((lane >> 3) & 1) * 8;
    const uint32_t v_noff = (lane >> 4) * 8;

    const int nkt = 2 * qt + 2;
    for (int kt = 0; kt < nkt; ++kt) {
        __syncthreads();
        // ---- load K (64x192) and V (64x128), hi+lo ----
        for (int idx = tid; idx < 64 * 24; idx += 256) {
            int r = idx / 24, u = idx % 24;
            int t = t0 + kt * 64 + r;
            const bf16 *srch, *srcl;
            if (u < 16) {
                size_t g = (size_t)t * (NHEADS * 256) + hh * 256 + u * 8;
                srch = kvh + g; srcl = kvl + g;
            } else {
                size_t g = (size_t)t * ROPE_D + (u - 16) * 8;
                srch = kpeh + g; srcl = kpel + g;
            }
            *(uint4*)(sm + FL_KH + r * FL_KSTR + u * 16) = *(const uint4*)srch;
            *(uint4*)(sm + FL_KL + r * FL_KSTR + u * 16) = *(const uint4*)srcl;
        }
        for (int idx = tid; idx < 64 * 16; idx += 256) {
            int r = idx / 16, u = idx % 16;
            size_t g = (size_t)(t0 + kt * 64 + r) * (NHEADS * 256) + hh * 256 + 128 + u * 8;
            *(uint4*)(sm + FL_VH + r * FL_VSTR + u * 16) = *(const uint4*)(kvh + g);
            *(uint4*)(sm + FL_VL + r * FL_VSTR + u * 16) = *(const uint4*)(kvl + g);
        }
        __syncthreads();

        // ---- QK: S(16x64) ----
        float s[8][4];
#pragma unroll
        for (int nf = 0; nf < 8; ++nf)
#pragma unroll
            for (int e = 0; e < 4; ++e) s[nf][e] = 0.f;

        for (int ks = 0; ks < 12; ++ks) {
            uint32_t aqh[4], aql[4];
            ldm4(aqh, sb + FL_QH + a_row * FL_QSTR + a_colb + ks * 32);
            ldm4(aql, sb + FL_QL + a_row * FL_QSTR + a_colb + ks * 32);
#pragma unroll
            for (int jb = 0; jb < 4; ++jb) {
                uint32_t bh4[4], bl4[4];
                uint32_t brow = jb * 16 + k_roff;
                ldm4(bh4, sb + FL_KH + brow * FL_KSTR + k_colb + ks * 32);
                mma16816(s[2*jb],   aqh, &bh4[0]);
                mma16816(s[2*jb+1], aqh, &bh4[2]);
                mma16816(s[2*jb],   aql, &bh4[0]);
                mma16816(s[2*jb+1], aql, &bh4[2]);
                ldm4(bl4, sb + FL_KL + brow * FL_KSTR + k_colb + ks * 32);
                mma16816(s[2*jb],   aqh, &bl4[0]);
                mma16816(s[2*jb+1], aqh, &bl4[2]);
            }
        }

        // ---- softmax ----
#pragma unroll
        for (int rr = 0; rr < 2; ++rr) {
            int grow = qt * 128 + wid * 16 + gid + rr * 8;
            float tmax = -1e30f;
#pragma unroll
            for (int nf = 0; nf < 8; ++nf) {
#pragma unroll
                for (int e = 0; e < 2; ++e) {
                    int gcol = kt * 64 + nf * 8 + tig * 2 + e;
                    float v = s[nf][rr * 2 + e] * sc;
                    if (gcol > grow) v = -1e30f;
                    s[nf][rr * 2 + e] = v;
                    tmax = fmaxf(tmax, v);
                }
            }
            tmax = fmaxf(tmax, __shfl_xor_sync(0xffffffffu, tmax, 1));
            tmax = fmaxf(tmax, __shfl_xor_sync(0xffffffffu, tmax, 2));
            float nm = fmaxf(m_i[rr], tmax);
            float fac = __expf(m_i[rr] - nm);
            float psum = 0.f;
#pragma unroll
            for (int nf = 0; nf < 8; ++nf) {
#pragma unroll
                for (int e = 0; e < 2; ++e) {
                    float p = __expf(s[nf][rr * 2 + e] - nm);
                    s[nf][rr * 2 + e] = p;
                    psum += p;
                }
            }
            psum += __shfl_xor_sync(0xffffffffu, psum, 1);
            psum += __shfl_xor_sync(0xffffffffu, psum, 2);
            l_i[rr] = l_i[rr] * fac + psum;
            m_i[rr] = nm;
#pragma unroll
            for (int nf = 0; nf < 16; ++nf) {
                O[nf][rr * 2] *= fac;
                O[nf][rr * 2 + 1] *= fac;
            }
        }

        // ---- write P hi/lo to smem ----
#pragma unroll
        for (int rr = 0; rr < 2; ++rr) {
            uint32_t prow = wid * 16 + gid + rr * 8;
#pragma unroll
            for (int nf = 0; nf < 8; ++nf) {
                float p0 = s[nf][rr * 2], p1 = s[nf][rr * 2 + 1];
                bf16 h0,l0,h1,l1;
                split1(p0, h0, l0); split1(p1, h1, l1);
                bf162 hp, lp; hp.x=h0; hp.y=h1; lp.x=l0; lp.y=l1;
                uint32_t off = prow * FL_PSTR + (nf * 8 + tig * 2) * 2;
                *(uint32_t*)(sm + FL_PH + off) = *(uint32_t*)&hp;
                *(uint32_t*)(sm + FL_PL + off) = *(uint32_t*)&lp;
            }
        }
        __syncthreads();

        // ---- AV: O += P(16x64) * V(64x128) ----
        for (int ks = 0; ks < 4; ++ks) {
            uint32_t aph[4], apl[4];
            ldm4(aph, sb + FL_PH + a_row * FL_PSTR + a_colb + ks * 32);
            ldm4(apl, sb + FL_PL + a_row * FL_PSTR + a_colb + ks * 32);
            uint32_t vrow = ks * 16 + v_koff;
#pragma unroll
            for (int nb = 0; nb < 8; ++nb) {
                uint32_t bvh[4], bvl[4];
                uint32_t vcol = (nb * 16 + v_noff) * 2;
                ldm4t(bvh, sb + FL_VH + vrow * FL_VSTR + vcol);
                mma16816(O[2*nb],   aph, &bvh[0]);
                mma16816(O[2*nb+1], aph, &bvh[2]);
                mma16816(O[2*nb],   apl, &bvh[0]);
                mma16816(O[2*nb+1], apl, &bvh[2]);
                ldm4t(bvl, sb + FL_VL + vrow * FL_VSTR + vcol);
                mma16816(O[2*nb],   aph, &bvl[0]);
                mma16816(O[2*nb+1], aph, &bvl[2]);
            }
        }
    }

    // ---- epilogue ----
#pragma unroll
    for (int rr = 0; rr < 2; ++rr) {
        float inv = 1.f / l_i[rr];
        int row = t0 + qt * 128 + wid * 16 + gid + rr * 8;
#pragma unroll
        for (int nf = 0; nf < 16; ++nf) {
            int col = nf * 8 + tig * 2;
            float v0 = O[nf][rr * 2] * inv, v1 = O[nf][rr * 2 + 1] * inv;
            bf16 h0,l0,h1,l1;
            split1(v0, h0, l0); split1(v1, h1, l1);
            bf162 hp, lp; hp.x=h0; hp.y=h1; lp.x=l0; lp.y=l1;
            size_t g = (size_t)row * (NHEADS * VHD) + hh * VHD + col;
            *(uint32_t*)(ctxh + g) = *(uint32_t*)&hp;
            *(uint32_t*)(ctxl + g) = *(uint32_t*)&lp;
        }
    }
}

// ---------------- launch ----------------
static inline void cvt(const float* x, bf16* h, bf16* l, int n) {
    int n4 = n >> 2;
    cvt_kernel<<<(n4 + 255) / 256, 256>>>(x, h, l, n4);
}

extern "C" void kernel_launch(void* const* d_in, const int* in_sizes, int n_in,
                              void* d_out, int out_size) {
    (void)in_sizes; (void)n_in; (void)out_size;
    const float* X     = (const float*)d_in[0];
    const int*   pos   = (const int*)  d_in[1];
    const float* wq_a  = (const float*)d_in[2];
    const float* qln   = (const float*)d_in[3];
    const float* wq_b  = (const float*)d_in[4];
    const float* wkv_a = (const float*)d_in[5];
    const float* kvln  = (const float*)d_in[6];
    const float* wkv_b = (const float*)d_in[7];
    const float* wo    = (const float*)d_in[8];
    float* out = (float*)d_out;

    float *qa, *ckv;
    bf16 *Xh,*Xl,*wqah,*wqal,*wqbh,*wqbl,*wkvah,*wkval,*wkvbh,*wkvbl,*woh,*wol;
    bf16 *qanh,*qanl,*ckvnh,*ckvnl,*qhb,*qlb,*kvh,*kvl,*kpeh,*kpel,*ctxh,*ctxl;
    cudaGetSymbolAddress((void**)&qa, g_qa);
    cudaGetSymbolAddress((void**)&ckv, g_ckv);
    cudaGetSymbolAddress((void**)&Xh, g_Xh);     cudaGetSymbolAddress((void**)&Xl, g_Xl);
    cudaGetSymbolAddress((void**)&wqah, g_wqa_h); cudaGetSymbolAddress((void**)&wqal, g_wqa_l);
    cudaGetSymbolAddress((void**)&wqbh, g_wqb_h); cudaGetSymbolAddress((void**)&wqbl, g_wqb_l);
    cudaGetSymbolAddress((void**)&wkvah, g_wkva_h); cudaGetSymbolAddress((void**)&wkval, g_wkva_l);
    cudaGetSymbolAddress((void**)&wkvbh, g_wkvb_h); cudaGetSymbolAddress((void**)&wkvbl, g_wkvb_l);
    cudaGetSymbolAddress((void**)&woh, g_wo_h);  cudaGetSymbolAddress((void**)&wol, g_wo_l);
    cudaGetSymbolAddress((void**)&qanh, g_qan_h); cudaGetSymbolAddress((void**)&qanl, g_qan_l);
    cudaGetSymbolAddress((void**)&ckvnh, g_ckvn_h); cudaGetSymbolAddress((void**)&ckvnl, g_ckvn_l);
    cudaGetSymbolAddress((void**)&qhb, g_qh);    cudaGetSymbolAddress((void**)&qlb, g_ql);
    cudaGetSymbolAddress((void**)&kvh, g_kvh);   cudaGetSymbolAddress((void**)&kvl, g_kvl);
    cudaGetSymbolAddress((void**)&kpeh, g_kpeh); cudaGetSymbolAddress((void**)&kpel, g_kpel);
    cudaGetSymbolAddress((void**)&ctxh, g_ctxh); cudaGetSymbolAddress((void**)&ctxl, g_ctxl);

    cudaFuncSetAttribute(bf_gemm, cudaFuncAttributeMaxDynamicSharedMemorySize, GEMM_SMEM);
    cudaFuncSetAttribute(flash_mma, cudaFuncAttributeMaxDynamicSharedMemorySize, FL_SMEM);

    const dim3 blk(256);
    const int mt = T_TOK / 128;  // 32

    // input conversions
    cvt(X, Xh, Xl, T_TOK * HIDDEN);
    cvt(wq_a, wqah, wqal, QLORA * HIDDEN);
    cvt(wq_b, wqbh, wqbl, NHEADS * QHD * QLORA);
    cvt(wkv_a, wkvah, wkval, KVW * HIDDEN);
    cvt(wkv_b, wkvbh, wkvbl, NHEADS * 256 * KVLORA);
    cvt(wo, woh, wol, HIDDEN * NHEADS * VHD);

    // q path
    bf_gemm<<<dim3(QLORA / 128, mt), blk, GEMM_SMEM>>>(Xh, Xl, wqah, wqal, qa, nullptr, nullptr,
                                                       T_TOK, QLORA, HIDDEN);
    rmsnorm_kernel<<<T_TOK, 256>>>(qa, qln, qanh, qanl, QLORA, QLORA);
    bf_gemm<<<dim3((NHEADS * QHD) / 128, mt), blk, GEMM_SMEM>>>(qanh, qanl, wqbh, wqbl,
                                                                nullptr, qhb, qlb,
                                                                T_TOK, NHEADS * QHD, QLORA);

    // kv path
    bf_gemm<<<dim3((KVW + 127) / 128, mt), blk, GEMM_SMEM>>>(Xh, Xl, wkvah, wkval, ckv,
                                                             nullptr, nullptr, T_TOK, KVW, HIDDEN);
    rmsnorm_kernel<<<T_TOK, 256>>>(ckv, kvln, ckvnh, ckvnl, KVLORA, KVW);
    rope_k_kernel<<<T_TOK, 32>>>(ckv, pos, kpeh, kpel);
    bf_gemm<<<dim3((NHEADS * 256) / 128, mt), blk, GEMM_SMEM>>>(ckvnh, ckvnl, wkvbh, wkvbl,
                                                                nullptr, kvh, kvl,
                                                                T_TOK, NHEADS * 256, KVLORA);

    // rope on q_pe (in place on hi/lo)
    rope_q_kernel<<<T_TOK * NHEADS, 32>>>(qhb, qlb, pos);

    // attention
    flash_mma<<<dim3(S_LEN / 128, NHEADS, BATCH), blk, FL_SMEM>>>(qhb, qlb, kvh, kvl,
                                                                  kpeh, kpel, ctxh, ctxl);

    // output projection
    bf_gemm<<<dim3(HIDDEN / 128, mt), blk, GEMM_SMEM>>>(ctxh, ctxl, woh, wol, out,
                                                        nullptr, nullptr,
                                                        T_TOK, HIDDEN, NHEADS * VHD);
}

// round 5
// speedup vs baseline: 3.6537x; 1.0789x over previous
#include <cuda_runtime.h>
#include <cuda_bf16.h>
#include <math.h>
#include <stdint.h>

// ---------------- problem constants ----------------
#define S_LEN   2048
#define BATCH   2
#define T_TOK   (BATCH * S_LEN)
#define HIDDEN  2048
#define QLORA   1536
#define KVLORA  512
#define NHEADS  16
#define NOPE    128
#define ROPE_D  64
#define QHD     192
#define VHD     128
#define KVW     576

typedef __nv_bfloat16 bf16;
typedef __nv_bfloat162 bf162;

// ---------------- scratch ----------------
__device__ float g_qa [T_TOK * QLORA];
__device__ float g_ckv[T_TOK * KVW];

__device__ bf16 g_Xh[T_TOK * HIDDEN],       g_Xl[T_TOK * HIDDEN];
__device__ bf16 g_wqa_h[QLORA * HIDDEN],    g_wqa_l[QLORA * HIDDEN];
__device__ bf16 g_wqb_h[NHEADS*QHD*QLORA],  g_wqb_l[NHEADS*QHD*QLORA];
__device__ bf16 g_wkva_h[KVW * HIDDEN],     g_wkva_l[KVW * HIDDEN];
__device__ bf16 g_wkvb_h[NHEADS*256*KVLORA],g_wkvb_l[NHEADS*256*KVLORA];
__device__ bf16 g_wo_h[HIDDEN*NHEADS*VHD],  g_wo_l[HIDDEN*NHEADS*VHD];
__device__ bf16 g_qan_h[T_TOK * QLORA],     g_qan_l[T_TOK * QLORA];
__device__ bf16 g_ckvn_h[T_TOK * KVLORA],   g_ckvn_l[T_TOK * KVLORA];
__device__ bf16 g_qh[T_TOK * NHEADS * QHD], g_ql[T_TOK * NHEADS * QHD];
__device__ bf16 g_kvh[T_TOK * NHEADS * 256],g_kvl[T_TOK * NHEADS * 256];
__device__ bf16 g_kpeh[T_TOK * ROPE_D],     g_kpel[T_TOK * ROPE_D];
__device__ bf16 g_ctxh[T_TOK * NHEADS*VHD], g_ctxl[T_TOK * NHEADS*VHD];

// ---------------- common helpers ----------------
__device__ __forceinline__ uint32_t smem_u32(const void* p) {
    uint32_t a;
    asm("{ .reg .u64 t; cvta.to.shared.u64 t, %1; cvt.u32.u64 %0, t; }" : "=r"(a) : "l"(p));
    return a;
}
__device__ __forceinline__ void ldm4(uint32_t* r, uint32_t addr) {
    asm volatile("ldmatrix.sync.aligned.m8n8.x4.shared.b16 {%0,%1,%2,%3}, [%4];"
                 : "=r"(r[0]), "=r"(r[1]), "=r"(r[2]), "=r"(r[3]) : "r"(addr));
}
__device__ __forceinline__ void ldm4t(uint32_t* r, uint32_t addr) {
    asm volatile("ldmatrix.sync.aligned.m8n8.x4.trans.shared.b16 {%0,%1,%2,%3}, [%4];"
                 : "=r"(r[0]), "=r"(r[1]), "=r"(r[2]), "=r"(r[3]) : "r"(addr));
}
__device__ __forceinline__ void mma16816(float* d, const uint32_t* a, const uint32_t* b) {
    asm volatile("mma.sync.aligned.m16n8k16.row.col.f32.bf16.bf16.f32 "
                 "{%0,%1,%2,%3}, {%4,%5,%6,%7}, {%8,%9}, {%0,%1,%2,%3};"
                 : "+f"(d[0]), "+f"(d[1]), "+f"(d[2]), "+f"(d[3])
                 : "r"(a[0]), "r"(a[1]), "r"(a[2]), "r"(a[3]), "r"(b[0]), "r"(b[1]));
}
__device__ __forceinline__ void cpa16(uint32_t dst, const void* src, uint32_t sz) {
    asm volatile("cp.async.cg.shared.global [%0], [%1], 16, %2;"
                 :: "r"(dst), "l"(src), "r"(sz) : "memory");
}
__device__ __forceinline__ void split1(float v, bf16& h, bf16& l) {
    h = __float2bfloat16_rn(v);
    l = __float2bfloat16_rn(v - __bfloat162float(h));
}

// ---------------- convert fp32 -> (hi, lo) bf16 ----------------
__global__ void cvt_kernel(const float* __restrict__ x, bf16* __restrict__ h,
                           bf16* __restrict__ l, int n4) {
    int i = blockIdx.x * blockDim.x + threadIdx.x;
    if (i >= n4) return;
    float4 v = ((const float4*)x)[i];
    bf16 h0,h1,h2,h3,l0,l1,l2,l3;
    split1(v.x,h0,l0); split1(v.y,h1,l1); split1(v.z,h2,l2); split1(v.w,h3,l3);
    bf162 hp0, hp1, lp0, lp1;
    hp0.x=h0; hp0.y=h1; hp1.x=h2; hp1.y=h3;
    lp0.x=l0; lp0.y=l1; lp1.x=l2; lp1.y=l3;
    uint2 hh, ll;
    hh.x=*(uint32_t*)&hp0; hh.y=*(uint32_t*)&hp1;
    ll.x=*(uint32_t*)&lp0; ll.y=*(uint32_t*)&lp1;
    ((uint2*)h)[i] = hh;
    ((uint2*)l)[i] = ll;
}

// ============================================================================
// bf16 split GEMM: C = A*B^T. BK=16, 4-stage cp.async, one sync per chunk.
// 128x128 CTA tile, 8 warps (64x32 warp tile), 2 CTAs/SM.
// ============================================================================
#define SMSTR 48                      // 16 bf16 = 32B + 16B pad
#define TILEB (128 * SMSTR)           // 6144
#define STAGEB (4 * TILEB)            // 24576 (Ah, Al, Bh, Bl)
#define NSTAGE 4
#define GEMM_SMEM (NSTAGE * STAGEB)   // 98304

__global__ __launch_bounds__(256, 2) void bf_gemm(
    const bf16* __restrict__ Ah, const bf16* __restrict__ Al,
    const bf16* __restrict__ Bh, const bf16* __restrict__ Bl,
    float* __restrict__ C, bf16* __restrict__ Ch, bf16* __restrict__ Cl,
    int M, int N, int K)
{
    extern __shared__ char sm[];
    const int tid = threadIdx.x;
    const int wid = tid >> 5;
    const int lane = tid & 31;
    const int m0 = blockIdx.y * 128;
    const int n0 = blockIdx.x * 128;
    const int nvalid = (N - n0 < 128) ? (N - n0) : 128;

    const uint32_t sbase = smem_u32(sm);
    const int wr = wid >> 2, wc = wid & 3;
    const uint32_t a_row = wr * 64 + (lane & 15);
    const uint32_t a_colb = (lane >> 4) * 16;
    const uint32_t b_row = wc * 32 + (lane & 7) + ((lane >> 4) << 3);
    const uint32_t b_colb = ((lane >> 3) & 1) * 16;

    float acc[4][4][4];
#pragma unroll
    for (int i = 0; i < 4; ++i)
#pragma unroll
        for (int j = 0; j < 4; ++j)
#pragma unroll
            for (int e = 0; e < 4; ++e) acc[i][j][e] = 0.f;

    const int nch = K >> 4;

    // per-thread copy: 4 x 16B per chunk. u = tid + i*256 in [0,1024)
    // tile=u>>8, row=(u&255)>>1, c16=u&1
    auto issue_chunk = [&](int c) {
        const int k0 = c << 4;
        const uint32_t stb = sbase + (c & (NSTAGE - 1)) * STAGEB;
#pragma unroll
        for (int i = 0; i < 4; ++i) {
            int u = tid + i * 256;
            int tile = u >> 8;
            int row = (u & 255) >> 1;
            int c16 = u & 1;
            uint32_t dst = stb + tile * TILEB + row * SMSTR + c16 * 16;
            const bf16* src;
            uint32_t sz = 16;
            if (tile == 0)      src = Ah + (size_t)(m0 + row) * K + k0 + c16 * 8;
            else if (tile == 1) src = Al + (size_t)(m0 + row) * K + k0 + c16 * 8;
            else {
                const bf16* base = (tile == 2) ? Bh : Bl;
                src = base + (size_t)(n0 + row) * K + k0 + c16 * 8;
                if (row >= nvalid) sz = 0;
            }
            cpa16(dst, src, sz);
        }
        asm volatile("cp.async.commit_group;" ::: "memory");
    };

    issue_chunk(0);
    if (nch > 1) issue_chunk(1); else asm volatile("cp.async.commit_group;" ::: "memory");
    if (nch > 2) issue_chunk(2); else asm volatile("cp.async.commit_group;" ::: "memory");

    for (int c = 0; c < nch; ++c) {
        asm volatile("cp.async.wait_group 2;" ::: "memory");
        __syncthreads();
        if (c + 3 < nch) issue_chunk(c + 3);
        else asm volatile("cp.async.commit_group;" ::: "memory");

        const uint32_t stb = sbase + (c & (NSTAGE - 1)) * STAGEB;
        uint32_t ah[4][4], bh[2][4];
#pragma unroll
        for (int i = 0; i < 4; ++i)
            ldm4(ah[i], stb + (a_row + i * 16) * SMSTR + a_colb);
#pragma unroll
        for (int jp = 0; jp < 2; ++jp)
            ldm4(bh[jp], stb + 2 * TILEB + (b_row + jp * 16) * SMSTR + b_colb);
#pragma unroll
        for (int i = 0; i < 4; ++i)
#pragma unroll
            for (int j = 0; j < 4; ++j)
                mma16816(acc[i][j], ah[i], &bh[j >> 1][(j & 1) * 2]);
        {
            uint32_t al[4][4];
#pragma unroll
            for (int i = 0; i < 4; ++i)
                ldm4(al[i], stb + TILEB + (a_row + i * 16) * SMSTR + a_colb);
#pragma unroll
            for (int i = 0; i < 4; ++i)
#pragma unroll
                for (int j = 0; j < 4; ++j)
                    mma16816(acc[i][j], al[i], &bh[j >> 1][(j & 1) * 2]);
        }
        {
            uint32_t bl[2][4];
#pragma unroll
            for (int jp = 0; jp < 2; ++jp)
                ldm4(bl[jp], stb + 3 * TILEB + (b_row + jp * 16) * SMSTR + b_colb);
#pragma unroll
            for (int i = 0; i < 4; ++i)
#pragma unroll
                for (int j = 0; j < 4; ++j)
                    mma16816(acc[i][j], ah[i], &bl[j >> 1][(j & 1) * 2]);
        }
    }

    // epilogue
    const int gid = lane >> 2, tig = lane & 3;
#pragma unroll
    for (int i = 0; i < 4; ++i) {
#pragma unroll
        for (int rr = 0; rr < 2; ++rr) {
            int row = m0 + wr * 64 + i * 16 + gid + rr * 8;
#pragma unroll
            for (int j = 0; j < 4; ++j) {
                int col = n0 + wc * 32 + j * 8 + tig * 2;
                if (col < N) {
                    float v0 = acc[i][j][rr * 2], v1 = acc[i][j][rr * 2 + 1];
                    if (C) *(float2*)(C + (size_t)row * N + col) = make_float2(v0, v1);
                    if (Ch) {
                        bf162 hp, lp;
                        bf16 h0,l0,h1,l1;
                        split1(v0,h0,l0); split1(v1,h1,l1);
                        hp.x=h0; hp.y=h1; lp.x=l0; lp.y=l1;
                        *(uint32_t*)(Ch + (size_t)row * N + col) = *(uint32_t*)&hp;
                        *(uint32_t*)(Cl + (size_t)row * N + col) = *(uint32_t*)&lp;
                    }
                }
            }
        }
    }
}

// ---------------- RMSNorm -> bf16 hi/lo ----------------
__global__ void rmsnorm_kernel(const float* __restrict__ x, const float* __restrict__ w,
                               bf16* __restrict__ yh, bf16* __restrict__ yl,
                               int D, int in_stride) {
    const int row = blockIdx.x;
    const float* xr = x + (size_t)row * in_stride;
    float ss = 0.f;
    for (int d = threadIdx.x; d < D; d += blockDim.x) { float v = xr[d]; ss += v * v; }
    __shared__ float red[32];
#pragma unroll
    for (int o = 16; o; o >>= 1) ss += __shfl_xor_sync(0xffffffffu, ss, o);
    if ((threadIdx.x & 31) == 0) red[threadIdx.x >> 5] = ss;
    __syncthreads();
    if (threadIdx.x < 32) {
        float v = (threadIdx.x < (blockDim.x >> 5)) ? red[threadIdx.x] : 0.f;
#pragma unroll
        for (int o = 16; o; o >>= 1) v += __shfl_xor_sync(0xffffffffu, v, o);
        if (threadIdx.x == 0) red[0] = v;
    }
    __syncthreads();
    float scale = rsqrtf(red[0] / (float)D + 1e-6f);
    for (int d = threadIdx.x; d < D; d += blockDim.x) {
        float v = w[d] * xr[d] * scale;
        bf16 h, l; split1(v, h, l);
        yh[(size_t)row * D + d] = h;
        yl[(size_t)row * D + d] = l;
    }
}

// ---------------- YaRN ----------------
__device__ __forceinline__ void yarn_cs(int pos, int j, float& c, float& s) {
    float ex   = __expf(-(float)(2 * j) * (9.210340371976184f / 64.f));
    float fi   = ex * 0.025f;
    float ramp = ((float)j - 10.f) * (1.f / 13.f);
    ramp = fminf(fmaxf(ramp, 0.f), 1.f);
    float invf = fi * ramp + ex * (1.f - ramp);
    float ang  = (float)pos * invf;
    c = cosf(ang); s = sinf(ang);
}

__global__ void rope_k_kernel(const float* __restrict__ ckv, const int* __restrict__ pos_ids,
                              bf16* __restrict__ kh, bf16* __restrict__ kl) {
    const int t = blockIdx.x;
    const int j = threadIdx.x;
    const int pos = pos_ids[t];
    const float* x = ckv + (size_t)t * KVW + KVLORA;
    float c, s; yarn_cs(pos, j, c, s);
    float x0 = x[2 * j], x1 = x[2 * j + 1];
    float r0 = x0 * c - x1 * s, r1 = x1 * c + x0 * s;
    bf16 h, l;
    split1(r0, h, l); kh[t * ROPE_D + j] = h;      kl[t * ROPE_D + j] = l;
    split1(r1, h, l); kh[t * ROPE_D + 32 + j] = h; kl[t * ROPE_D + 32 + j] = l;
}

__global__ void rope_q_kernel(bf16* __restrict__ qh, bf16* __restrict__ ql,
                              const int* __restrict__ pos_ids) {
    const int t = blockIdx.x >> 4;
    const int h = blockIdx.x & 15;
    const int j = threadIdx.x;
    const int pos = pos_ids[t];
    bf16* xh = qh + (size_t)t * (NHEADS * QHD) + h * QHD + NOPE;
    bf16* xl = ql + (size_t)t * (NHEADS * QHD) + h * QHD + NOPE;
    float c, s; yarn_cs(pos, j, c, s);
    float x0 = __bfloat162float(xh[2*j])   + __bfloat162float(xl[2*j]);
    float x1 = __bfloat162float(xh[2*j+1]) + __bfloat162float(xl[2*j+1]);
    float r0 = x0 * c - x1 * s, r1 = x1 * c + x0 * s;
    __syncwarp();
    bf16 hh, ll;
    split1(r0, hh, ll); xh[j] = hh;      xl[j] = ll;
    split1(r1, hh, ll); xh[32 + j] = hh; xl[32 + j] = ll;
}

// ============================================================================
// Flash attention, split-bf16 HMMA. BM=128, BN=64, 8 warps.
// Q fragments register-resident; K/V double-buffered via cp.async.
// smem: 2 KV stages (each: KH,KL 64x400; VH,VL 64x272) + P hi/lo (128x144).
// ============================================================================
#define FL_KSTR 400
#define FL_VSTR 272
#define FL_PSTR 144
#define FL_KVSTG (64 * FL_KSTR * 2 + 64 * FL_VSTR * 2)   // 86016
#define FL_VOFF  (64 * FL_KSTR * 2)                      // V base within stage
#define FL_PH  (2 * FL_KVSTG)                            // 172032
#define FL_PL  (FL_PH + 128 * FL_PSTR)                   // 190464
#define FL_SMEM (FL_PL + 128 * FL_PSTR)                  // 208896
// Q staging (prologue only, overlaps KV stages): hi at 0, lo at 51200
#define FL_QSTR 400

__global__ __launch_bounds__(256, 1) void flash_mma(
    const bf16* __restrict__ qh, const bf16* __restrict__ ql,
    const bf16* __restrict__ kvh, const bf16* __restrict__ kvl,
    const bf16* __restrict__ kpeh, const bf16* __restrict__ kpel,
    bf16* __restrict__ ctxh, bf16* __restrict__ ctxl)
{
    extern __shared__ char sm[];
    const uint32_t sb = smem_u32(sm);
    const int qt = (int)gridDim.x - 1 - (int)blockIdx.x;   // heavy tiles first
    const int hh = blockIdx.y, b = blockIdx.z;
    const int tid = threadIdx.x, wid = tid >> 5, lane = tid & 31;
    const int gid = lane >> 2, tig = lane & 3;
    const int t0 = b * S_LEN;

    const uint32_t a_row = wid * 16 + (lane & 15);
    const uint32_t a_colb = (lane >> 4) * 16;
    const uint32_t k_roff = (lane & 7) + ((lane >> 4) << 3);
    const uint32_t k_colb = ((lane >> 3) & 1) * 16;
    const uint32_t v_koff = (lane & 7) + ((lane >> 3) & 1) * 8;
    const uint32_t v_noff = (lane >> 4) * 8;

    // ---- stage Q (128x192 hi+lo) into smem, pull fragments to registers ----
    for (int idx = tid; idx < 128 * 24; idx += 256) {
        int r = idx / 24, u = idx % 24;
        size_t g = (size_t)(t0 + qt * 128 + r) * (NHEADS * QHD) + hh * QHD + u * 8;
        *(uint4*)(sm + r * FL_QSTR + u * 16) = *(const uint4*)(qh + g);
        *(uint4*)(sm + 51200 + r * FL_QSTR + u * 16) = *(const uint4*)(ql + g);
    }
    __syncthreads();
    uint32_t qfh[12][4], qfl[12][4];
#pragma unroll
    for (int ks = 0; ks < 12; ++ks) {
        ldm4(qfh[ks], sb + a_row * FL_QSTR + a_colb + ks * 32);
        ldm4(qfl[ks], sb + 51200 + a_row * FL_QSTR + a_colb + ks * 32);
    }
    __syncthreads();   // Q staging free; KV pipeline may overwrite

    // KV tile load via cp.async: per thread 20 x 16B
    auto issue_kv = [&](int kt) {
        const uint32_t stb = sb + (kt & 1) * FL_KVSTG;
        // K: 64 rows x 24 u-units (16 kv + 8 rope), hi+lo interleaved by unit idx
        for (int idx = tid; idx < 64 * 24; idx += 256) {
            int r = idx / 24, u = idx % 24;
            int t = t0 + kt * 64 + r;
            const bf16 *srch, *srcl;
            if (u < 16) {
                size_t g = (size_t)t * (NHEADS * 256) + hh * 256 + u * 8;
                srch = kvh + g; srcl = kvl + g;
            } else {
                size_t g = (size_t)t * ROPE_D + (u - 16) * 8;
                srch = kpeh + g; srcl = kpel + g;
            }
            uint32_t off = r * FL_KSTR + u * 16;
            cpa16(stb + off, srch, 16);
            cpa16(stb + 64 * FL_KSTR + off, srcl, 16);
        }
        // V: 64 rows x 16 units
        for (int idx = tid; idx < 64 * 16; idx += 256) {
            int r = idx >> 4, u = idx & 15;
            size_t g = (size_t)(t0 + kt * 64 + r) * (NHEADS * 256) + hh * 256 + 128 + u * 8;
            uint32_t off = FL_VOFF + r * FL_VSTR + u * 16;
            cpa16(stb + off, kvh + g, 16);
            cpa16(stb + 64 * FL_VSTR + off, kvl + g, 16);
        }
        asm volatile("cp.async.commit_group;" ::: "memory");
    };

    float m_i[2], l_i[2], O[16][4];
    m_i[0] = m_i[1] = -1e30f; l_i[0] = l_i[1] = 0.f;
#pragma unroll
    for (int nf = 0; nf < 16; ++nf)
#pragma unroll
        for (int e = 0; e < 4; ++e) O[nf][e] = 0.f;

    const float mm = 0.1f * logf(40.f) + 1.f;
    const float sc = mm * mm * rsqrtf(192.f);

    const int nkt = 2 * qt + 2;
    issue_kv(0);

    for (int kt = 0; kt < nkt; ++kt) {
        if (kt + 1 < nkt) {
            issue_kv(kt + 1);
            asm volatile("cp.async.wait_group 1;" ::: "memory");
        } else {
            asm volatile("cp.async.wait_group 0;" ::: "memory");
        }
        __syncthreads();
        const uint32_t stb = sb + (kt & 1) * FL_KVSTG;

        // ---- QK ----
        float s[8][4];
#pragma unroll
        for (int nf = 0; nf < 8; ++nf)
#pragma unroll
            for (int e = 0; e < 4; ++e) s[nf][e] = 0.f;

#pragma unroll
        for (int ks = 0; ks < 12; ++ks) {
#pragma unroll
            for (int jb = 0; jb < 4; ++jb) {
                uint32_t bh4[4], bl4[4];
                uint32_t brow = jb * 16 + k_roff;
                ldm4(bh4, stb + brow * FL_KSTR + k_colb + ks * 32);
                mma16816(s[2*jb],   qfh[ks], &bh4[0]);
                mma16816(s[2*jb+1], qfh[ks], &bh4[2]);
                mma16816(s[2*jb],   qfl[ks], &bh4[0]);
                mma16816(s[2*jb+1], qfl[ks], &bh4[2]);
                ldm4(bl4, stb + 64 * FL_KSTR + brow * FL_KSTR + k_colb + ks * 32);
                mma16816(s[2*jb],   qfh[ks], &bl4[0]);
                mma16816(s[2*jb+1], qfh[ks], &bl4[2]);
            }
        }

        // ---- softmax ----
#pragma unroll
        for (int rr = 0; rr < 2; ++rr) {
            int grow = qt * 128 + wid * 16 + gid + rr * 8;
            float tmax = -1e30f;
#pragma unroll
            for (int nf = 0; nf < 8; ++nf) {
#pragma unroll
                for (int e = 0; e < 2; ++e) {
                    int gcol = kt * 64 + nf * 8 + tig * 2 + e;
                    float v = s[nf][rr * 2 + e] * sc;
                    if (gcol > grow) v = -1e30f;
                    s[nf][rr * 2 + e] = v;
                    tmax = fmaxf(tmax, v);
                }
            }
            tmax = fmaxf(tmax, __shfl_xor_sync(0xffffffffu, tmax, 1));
            tmax = fmaxf(tmax, __shfl_xor_sync(0xffffffffu, tmax, 2));
            float nm = fmaxf(m_i[rr], tmax);
            float fac = __expf(m_i[rr] - nm);
            float psum = 0.f;
#pragma unroll
            for (int nf = 0; nf < 8; ++nf) {
#pragma unroll
                for (int e = 0; e < 2; ++e) {
                    float p = __expf(s[nf][rr * 2 + e] - nm);
                    s[nf][rr * 2 + e] = p;
                    psum += p;
                }
            }
            psum += __shfl_xor_sync(0xffffffffu, psum, 1);
            psum += __shfl_xor_sync(0xffffffffu, psum, 2);
            l_i[rr] = l_i[rr] * fac + psum;
            m_i[rr] = nm;
#pragma unroll
            for (int nf = 0; nf < 16; ++nf) {
                O[nf][rr * 2] *= fac;
                O[nf][rr * 2 + 1] *= fac;
            }
        }

        // ---- P hi/lo to smem (warp-private rows) ----
#pragma unroll
        for (int rr = 0; rr < 2; ++rr) {
            uint32_t prow = wid * 16 + gid + rr * 8;
#pragma unroll
            for (int nf = 0; nf < 8; ++nf) {
                float p0 = s[nf][rr * 2], p1 = s[nf][rr * 2 + 1];
                bf16 h0,l0,h1,l1;
                split1(p0, h0, l0); split1(p1, h1, l1);
                bf162 hp, lp; hp.x=h0; hp.y=h1; lp.x=l0; lp.y=l1;
                uint32_t off = prow * FL_PSTR + (nf * 8 + tig * 2) * 2;
                *(uint32_t*)(sm + FL_PH + off) = *(uint32_t*)&hp;
                *(uint32_t*)(sm + FL_PL + off) = *(uint32_t*)&lp;
            }
        }
        __syncwarp();

        // ---- AV ----
#pragma unroll
        for (int ks = 0; ks < 4; ++ks) {
            uint32_t aph[4], apl[4];
            ldm4(aph, sb + FL_PH + a_row * FL_PSTR + a_colb + ks * 32);
            ldm4(apl, sb + FL_PL + a_row * FL_PSTR + a_colb + ks * 32);
            uint32_t vrow = ks * 16 + v_koff;
#pragma unroll
            for (int nb = 0; nb < 8; ++nb) {
                uint32_t bvh[4], bvl[4];
                uint32_t vcol = (nb * 16 + v_noff) * 2;
                ldm4t(bvh, stb + FL_VOFF + vrow * FL_VSTR + vcol);
                mma16816(O[2*nb],   aph, &bvh[0]);
                mma16816(O[2*nb+1], aph, &bvh[2]);
                mma16816(O[2*nb],   apl, &bvh[0]);
                mma16816(O[2*nb+1], apl, &bvh[2]);
                ldm4t(bvl, stb + FL_VOFF + 64 * FL_VSTR + vrow * FL_VSTR + vcol);
                mma16816(O[2*nb],   aph, &bvl[0]);
                mma16816(O[2*nb+1], aph, &bvl[2]);
            }
        }
        __syncthreads();   // all reads of stage kt&1 done before reuse
    }

    // ---- epilogue ----
#pragma unroll
    for (int rr = 0; rr < 2; ++rr) {
        float inv = 1.f / l_i[rr];
        int row = t0 + qt * 128 + wid * 16 + gid + rr * 8;
#pragma unroll
        for (int nf = 0; nf < 16; ++nf) {
            int col = nf * 8 + tig * 2;
            float v0 = O[nf][rr * 2] * inv, v1 = O[nf][rr * 2 + 1] * inv;
            bf16 h0,l0,h1,l1;
            split1(v0, h0, l0); split1(v1, h1, l1);
            bf162 hp, lp; hp.x=h0; hp.y=h1; lp.x=l0; lp.y=l1;
            size_t g = (size_t)row * (NHEADS * VHD) + hh * VHD + col;
            *(uint32_t*)(ctxh + g) = *(uint32_t*)&hp;
            *(uint32_t*)(ctxl + g) = *(uint32_t*)&lp;
        }
    }
}

// ---------------- launch ----------------
static inline void cvt(const float* x, bf16* h, bf16* l, int n) {
    int n4 = n >> 2;
    cvt_kernel<<<(n4 + 255) / 256, 256>>>(x, h, l, n4);
}

extern "C" void kernel_launch(void* const* d_in, const int* in_sizes, int n_in,
                              void* d_out, int out_size) {
    (void)in_sizes; (void)n_in; (void)out_size;
    const float* X     = (const float*)d_in[0];
    const int*   pos   = (const int*)  d_in[1];
    const float* wq_a  = (const float*)d_in[2];
    const float* qln   = (const float*)d_in[3];
    const float* wq_b  = (const float*)d_in[4];
    const float* wkv_a = (const float*)d_in[5];
    const float* kvln  = (const float*)d_in[6];
    const float* wkv_b = (const float*)d_in[7];
    const float* wo    = (const float*)d_in[8];
    float* out = (float*)d_out;

    float *qa, *ckv;
    bf16 *Xh,*Xl,*wqah,*wqal,*wqbh,*wqbl,*wkvah,*wkval,*wkvbh,*wkvbl,*woh,*wol;
    bf16 *qanh,*qanl,*ckvnh,*ckvnl,*qhb,*qlb,*kvh,*kvl,*kpeh,*kpel,*ctxh,*ctxl;
    cudaGetSymbolAddress((void**)&qa, g_qa);
    cudaGetSymbolAddress((void**)&ckv, g_ckv);
    cudaGetSymbolAddress((void**)&Xh, g_Xh);     cudaGetSymbolAddress((void**)&Xl, g_Xl);
    cudaGetSymbolAddress((void**)&wqah, g_wqa_h); cudaGetSymbolAddress((void**)&wqal, g_wqa_l);
    cudaGetSymbolAddress((void**)&wqbh, g_wqb_h); cudaGetSymbolAddress((void**)&wqbl, g_wqb_l);
    cudaGetSymbolAddress((void**)&wkvah, g_wkva_h); cudaGetSymbolAddress((void**)&wkval, g_wkva_l);
    cudaGetSymbolAddress((void**)&wkvbh, g_wkvb_h); cudaGetSymbolAddress((void**)&wkvbl, g_wkvb_l);
    cudaGetSymbolAddress((void**)&woh, g_wo_h);  cudaGetSymbolAddress((void**)&wol, g_wo_l);
    cudaGetSymbolAddress((void**)&qanh, g_qan_h); cudaGetSymbolAddress((void**)&qanl, g_qan_l);
    cudaGetSymbolAddress((void**)&ckvnh, g_ckvn_h); cudaGetSymbolAddress((void**)&ckvnl, g_ckvn_l);
    cudaGetSymbolAddress((void**)&qhb, g_qh);    cudaGetSymbolAddress((void**)&qlb, g_ql);
    cudaGetSymbolAddress((void**)&kvh, g_kvh);   cudaGetSymbolAddress((void**)&kvl, g_kvl);
    cudaGetSymbolAddress((void**)&kpeh, g_kpeh); cudaGetSymbolAddress((void**)&kpel, g_kpel);
    cudaGetSymbolAddress((void**)&ctxh, g_ctxh); cudaGetSymbolAddress((void**)&ctxl, g_ctxl);

    cudaFuncSetAttribute(bf_gemm, cudaFuncAttributeMaxDynamicSharedMemorySize, GEMM_SMEM);
    cudaFuncSetAttribute(flash_mma, cudaFuncAttributeMaxDynamicSharedMemorySize, FL_SMEM);

    const dim3 blk(256);
    const int mt = T_TOK / 128;  // 32

    // input conversions
    cvt(X, Xh, Xl, T_TOK * HIDDEN);
    cvt(wq_a, wqah, wqal, QLORA * HIDDEN);
    cvt(wq_b, wqbh, wqbl, NHEADS * QHD * QLORA);
    cvt(wkv_a, wkvah, wkval, KVW * HIDDEN);
    cvt(wkv_b, wkvbh, wkvbl, NHEADS * 256 * KVLORA);
    cvt(wo, woh, wol, HIDDEN * NHEADS * VHD);

    // q path
    bf_gemm<<<dim3(QLORA / 128, mt), blk, GEMM_SMEM>>>(Xh, Xl, wqah, wqal, qa, nullptr, nullptr,
                                                       T_TOK, QLORA, HIDDEN);
    rmsnorm_kernel<<<T_TOK, 256>>>(qa, qln, qanh, qanl, QLORA, QLORA);
    bf_gemm<<<dim3((NHEADS * QHD) / 128, mt), blk, GEMM_SMEM>>>(qanh, qanl, wqbh, wqbl,
                                                                nullptr, qhb, qlb,
                                                                T_TOK, NHEADS * QHD, QLORA);

    // kv path
    bf_gemm<<<dim3((KVW + 127) / 128, mt), blk, GEMM_SMEM>>>(Xh, Xl, wkvah, wkval, ckv,
                                                             nullptr, nullptr, T_TOK, KVW, HIDDEN);
    rmsnorm_kernel<<<T_TOK, 256>>>(ckv, kvln, ckvnh, ckvnl, KVLORA, KVW);
    rope_k_kernel<<<T_TOK, 32>>>(ckv, pos, kpeh, kpel);
    bf_gemm<<<dim3((NHEADS * 256) / 128, mt), blk, GEMM_SMEM>>>(ckvnh, ckvnl, wkvbh, wkvbl,
                                                                nullptr, kvh, kvl,
                                                                T_TOK, NHEADS * 256, KVLORA);

    // rope on q_pe (in place on hi/lo)
    rope_q_kernel<<<T_TOK * NHEADS, 32>>>(qhb, qlb, pos);

    // attention
    flash_mma<<<dim3(S_LEN / 128, NHEADS, BATCH), blk, FL_SMEM>>>(qhb, qlb, kvh, kvl,
                                                                  kpeh, kpel, ctxh, ctxl);

    // output projection
    bf_gemm<<<dim3(HIDDEN / 128, mt), blk, GEMM_SMEM>>>(ctxh, ctxl, woh, wol, out,
                                                        nullptr, nullptr,
                                                        T_TOK, HIDDEN, NHEADS * VHD);
}